// round 8
// baseline (speedup 1.0000x reference)
#include <cuda_runtime.h>
#include <cuda_bf16.h>
#include <cstdint>

#define B_     8
#define C_     128
#define PIXPB  36864
#define NPIX   294912
#define NT     2304             // 128-pixel tiles
#define TPB    288              // tiles per batch
#define EPS    1e-6f
#define GRID_A 296
#define GRID_B 148
#define SA     304              // A-tile row stride bytes (conflict-free)

// ---------------- device globals (no allocation) ----------------
__device__ uint32_t g_s[(size_t)NPIX * 64];   // gated branch bf16x2 [pix][64]
__device__ float    g_gpart[NT * 128];        // per-tile GAP partials
__device__ float    g_att[B_ * C_];
// mma.sync B-fragment images: [ks][nb][lane][e] uint32 (bf16x2) -> uint2 per lane
__device__ uint32_t g_fw1 [8 * 32 * 32 * 2];  // w1  (pair-permuted), N=256
__device__ uint32_t g_fwf1[8 * 32 * 32 * 2];  // wf1 (pair-permuted), N=256
__device__ uint32_t g_fw2 [8 * 16 * 32 * 2];  // w2, N=128
__device__ uint32_t g_fwf2[8 * 16 * 32 * 2];  // wf2, N=128

__device__ __forceinline__ uint32_t pack_bf2(float a, float b) {
    __nv_bfloat162 h = __floats2bfloat162_rn(a, b);   // low = a
    return *reinterpret_cast<uint32_t*>(&h);
}
__device__ __forceinline__ float2 unpack_bf2(uint32_t w) {
    __nv_bfloat162 h = *reinterpret_cast<const __nv_bfloat162*>(&w);
    return make_float2(__low2float(h), __high2float(h));
}
__device__ __forceinline__ void mma_bf16(float* c, uint32_t a0, uint32_t a1,
                                         uint32_t a2, uint32_t a3,
                                         uint32_t b0, uint32_t b1) {
    asm volatile(
        "mma.sync.aligned.m16n8k16.row.col.f32.bf16.bf16.f32 "
        "{%0,%1,%2,%3}, {%4,%5,%6,%7}, {%8,%9}, {%0,%1,%2,%3};\n"
        : "+f"(c[0]), "+f"(c[1]), "+f"(c[2]), "+f"(c[3])
        : "r"(a0), "r"(a1), "r"(a2), "r"(a3), "r"(b0), "r"(b1));
}
__device__ __forceinline__ uint32_t smem_u32(const void* p) {
    uint32_t a;
    asm("{ .reg .u64 t; cvta.to.shared.u64 t, %1; cvt.u32.u64 %0, t; }" : "=r"(a) : "l"(p));
    return a;
}
#define CP_ASYNC16(dst, src) \
    asm volatile("cp.async.ca.shared.global [%0], [%1], 16;" :: "r"(dst), "l"(src))
#define CP_COMMIT()  asm volatile("cp.async.commit_group;" ::: "memory")
#define CP_WAIT1()   asm volatile("cp.async.wait_group 1;" ::: "memory")
#define CP_WAIT0()   asm volatile("cp.async.wait_group 0;" ::: "memory")

// =====================================================================
// k0: B-fragment images, [ks][nb][lane][e] so (b0,b1) is one uint2.
// =====================================================================
__global__ void k0_frags(const float* __restrict__ w1, const float* __restrict__ w2,
                         const float* __restrict__ wf1, const float* __restrict__ wf2)
{
    int i0 = blockIdx.x * blockDim.x + threadIdx.x, str = gridDim.x * blockDim.x;
    for (int i = i0; i < 8 * 32 * 32 * 2; i += str) {
        int e = i & 1, lane = (i >> 1) & 31, nb = (i >> 6) & 31, ks = i >> 11;
        int n = 8 * nb + (lane >> 2);
        int k = 16 * ks + 2 * (lane & 3) + 8 * e;
        int o = (n >> 1) + (n & 1) * 128;
        g_fw1 [i] = pack_bf2(w1 [k * 256 + o], w1 [(k + 1) * 256 + o]);
        g_fwf1[i] = pack_bf2(wf1[k * 256 + o], wf1[(k + 1) * 256 + o]);
    }
    for (int i = i0; i < 8 * 16 * 32 * 2; i += str) {
        int e = i & 1, lane = (i >> 1) & 31, nb = (i >> 6) & 15, ks = i >> 10;
        int n = 8 * nb + (lane >> 2);
        int k = 16 * ks + 2 * (lane & 3) + 8 * e;
        g_fw2 [i] = pack_bf2(w2 [k * 128 + n], w2 [(k + 1) * 128 + n]);
        g_fwf2[i] = pack_bf2(wf2[k * 128 + n], wf2[(k + 1) * 128 + n]);
    }
}

// =====================================================================
// kA: 128 thr, 4 warps x 32 rows. LN1 -> mma(w1, 2 x n128) -> gate -> g_s
//     + per-tile GAP. 2 CTAs/SM.
// =====================================================================
#define KA_FW1  38912
#define KA_EW   (KA_FW1 + 65536)
#define KA_LN   (KA_EW + 2048)
#define KA_GAP  (KA_LN + 1024)
#define KA_SMEM (KA_GAP + 4096)   // 111616

__global__ void __launch_bounds__(128, 2)
kA_spatial(const float* __restrict__ x,
           const float* __restrict__ ln1s, const float* __restrict__ ln1b,
           const float* __restrict__ b1,   const float* __restrict__ wdw,
           const float* __restrict__ bdw)
{
    extern __shared__ char sm[];
    const int tid = threadIdx.x, lane = tid & 31, warp = tid >> 5;
    const int q = lane & 3, r = lane >> 2, m0 = warp * 32;

    {
        uint4* dst = (uint4*)(sm + KA_FW1);
        const uint4* src = (const uint4*)g_fw1;
        for (int i = tid; i < 4096; i += 128) dst[i] = src[i];
        int n = tid, o = (n >> 1) + (n & 1) * 128;
        float w = wdw[o];
        ((float2*)(sm + KA_EW))[n] = make_float2(w, b1[o] * w + bdw[o]);
        n = tid + 128; o = (n >> 1) + (n & 1) * 128;
        w = wdw[o];
        ((float2*)(sm + KA_EW))[n] = make_float2(w, b1[o] * w + bdw[o]);
        ((float2*)(sm + KA_LN))[tid] = make_float2(ln1s[tid], ln1b[tid]);
    }
    __syncthreads();

    const float2* ewp = (const float2*)(sm + KA_EW);
    const float2* lnp = (const float2*)(sm + KA_LN);
    float* gapw = (float*)(sm + KA_GAP);

    for (int tile = blockIdx.x; tile < NT; tile += GRID_A) {
        // ---- LN1: thread = pixel tid, two passes over x row ----
        const float4* xr = (const float4*)x + ((size_t)(tile * 128 + tid)) * 32;
        float s1 = 0.f, s2 = 0.f;
        #pragma unroll
        for (int i = 0; i < 32; ++i) {
            float4 v = xr[i];
            s1 += v.x + v.y + v.z + v.w;
            s2 += v.x*v.x + v.y*v.y + v.z*v.z + v.w*v.w;
        }
        const float mu = s1 * (1.f/128.f);
        const float rs = rsqrtf(fmaxf(s2 * (1.f/128.f) - mu*mu, 0.f) + EPS);

        char* rowb = sm + tid * SA;
        #pragma unroll
        for (int j = 0; j < 16; ++j) {
            float4 v0 = xr[2*j], v1 = xr[2*j+1];
            int c = 8 * j;
            float2 p0 = lnp[c],   p1 = lnp[c+1], p2 = lnp[c+2], p3 = lnp[c+3];
            float2 p4 = lnp[c+4], p5 = lnp[c+5], p6 = lnp[c+6], p7 = lnp[c+7];
            uint4 o;
            o.x = pack_bf2((v0.x-mu)*rs*p0.x+p0.y, (v0.y-mu)*rs*p1.x+p1.y);
            o.y = pack_bf2((v0.z-mu)*rs*p2.x+p2.y, (v0.w-mu)*rs*p3.x+p3.y);
            o.z = pack_bf2((v1.x-mu)*rs*p4.x+p4.y, (v1.y-mu)*rs*p5.x+p5.y);
            o.w = pack_bf2((v1.z-mu)*rs*p6.x+p6.y, (v1.w-mu)*rs*p7.x+p7.y);
            *(uint4*)(rowb + j * 16) = o;
        }
        __syncwarp();

        const char* arA = sm + (m0 + r) * SA;
        const char* arB = arA + 16 * SA;
        uint32_t gs0[2][16];

        #pragma unroll 1
        for (int half = 0; half < 2; ++half) {
            float acc[2][16][4];
            #pragma unroll
            for (int t = 0; t < 2; ++t)
                #pragma unroll
                for (int nb = 0; nb < 16; ++nb)
                    { acc[t][nb][0]=0.f; acc[t][nb][1]=0.f; acc[t][nb][2]=0.f; acc[t][nb][3]=0.f; }

            #pragma unroll 1
            for (int ks = 0; ks < 8; ++ks) {
                int kb = 32 * ks + 4 * q;
                uint32_t a00 = *(const uint32_t*)(arA + kb);
                uint32_t a01 = *(const uint32_t*)(arA + 8 * SA + kb);
                uint32_t a02 = *(const uint32_t*)(arA + kb + 16);
                uint32_t a03 = *(const uint32_t*)(arA + 8 * SA + kb + 16);
                uint32_t a10 = *(const uint32_t*)(arB + kb);
                uint32_t a11 = *(const uint32_t*)(arB + 8 * SA + kb);
                uint32_t a12 = *(const uint32_t*)(arB + kb + 16);
                uint32_t a13 = *(const uint32_t*)(arB + 8 * SA + kb + 16);
                const uint2* fb = (const uint2*)(sm + KA_FW1) + ks * 1024 + half * 512 + lane;
                #pragma unroll
                for (int nb = 0; nb < 16; ++nb) {
                    uint2 b = fb[nb * 32];
                    mma_bf16(acc[0][nb], a00, a01, a02, a03, b.x, b.y);
                    mma_bf16(acc[1][nb], a10, a11, a12, a13, b.x, b.y);
                }
            }

            #pragma unroll
            for (int nb = 0; nb < 16; ++nb) {
                int nbg = half * 16 + nb;
                int n0 = 8 * nbg + 2 * q, j = 4 * nbg + q;
                float2 e0 = ewp[n0], e1 = ewp[n0 + 1];
                float lo0 = (acc[0][nb][0]*e0.x + e0.y) * (acc[0][nb][1]*e1.x + e1.y);
                float hi0 = (acc[0][nb][2]*e0.x + e0.y) * (acc[0][nb][3]*e1.x + e1.y);
                float lo1 = (acc[1][nb][0]*e0.x + e0.y) * (acc[1][nb][1]*e1.x + e1.y);
                float hi1 = (acc[1][nb][2]*e0.x + e0.y) * (acc[1][nb][3]*e1.x + e1.y);
                float g = (lo0 + hi0) + (lo1 + hi1);
                g += __shfl_xor_sync(0xffffffffu, g, 4);
                g += __shfl_xor_sync(0xffffffffu, g, 8);
                g += __shfl_xor_sync(0xffffffffu, g, 16);
                if (r == 0) gapw[warp * 128 + j] = g;
                if (half == 0) {
                    gs0[0][nb] = pack_bf2(lo0, hi0);
                    gs0[1][nb] = pack_bf2(lo1, hi1);
                } else {
                    *(__nv_bfloat16*)(sm + (m0 + r)      * SA + j * 2) = __float2bfloat16(lo0);
                    *(__nv_bfloat16*)(sm + (m0 + r + 8)  * SA + j * 2) = __float2bfloat16(hi0);
                    *(__nv_bfloat16*)(sm + (m0 + r + 16) * SA + j * 2) = __float2bfloat16(lo1);
                    *(__nv_bfloat16*)(sm + (m0 + r + 24) * SA + j * 2) = __float2bfloat16(hi1);
                }
            }
            __syncwarp();
        }
        #pragma unroll
        for (int nb = 0; nb < 16; ++nb) {
            int j = 4 * nb + q;
            float2 v0 = unpack_bf2(gs0[0][nb]);
            float2 v1 = unpack_bf2(gs0[1][nb]);
            *(__nv_bfloat16*)(sm + (m0 + r)      * SA + j * 2) = __float2bfloat16(v0.x);
            *(__nv_bfloat16*)(sm + (m0 + r + 8)  * SA + j * 2) = __float2bfloat16(v0.y);
            *(__nv_bfloat16*)(sm + (m0 + r + 16) * SA + j * 2) = __float2bfloat16(v1.x);
            *(__nv_bfloat16*)(sm + (m0 + r + 24) * SA + j * 2) = __float2bfloat16(v1.y);
        }
        __syncwarp();

        // ---- coalesced copy to g_s (warp-local 32 rows) ----
        #pragma unroll
        for (int i = 0; i < 16; ++i) {
            int u = lane + 32 * i, row = u >> 4, ch = u & 15;
            uint4 v = *(const uint4*)(sm + (m0 + row) * SA + ch * 16);
            ((uint4*)g_s)[((size_t)(tile * 128 + m0 + row)) * 16 + ch] = v;
        }

        __syncthreads();
        if (tid < 128) {
            float s = 0.f;
            #pragma unroll
            for (int w = 0; w < 4; ++w) s += gapw[w * 128 + tid];
            g_gpart[tile * 128 + tid] = s;
        }
        __syncthreads();
    }
}

// =====================================================================
// k2_se: parallel reduce of 288 per-tile partials per batch + SE dense
// =====================================================================
__global__ void k2_se(const float* __restrict__ wse, const float* __restrict__ bse)
{
    __shared__ float red[4][128];
    __shared__ float gap[128];
    const int b = blockIdx.x, tid = threadIdx.x;
    const int c = tid & 127, g = tid >> 7;
    float s = 0.f;
    const float* src = g_gpart + (size_t)(b * TPB + g * 72) * 128 + c;
    #pragma unroll 8
    for (int i = 0; i < 72; ++i) s += src[(size_t)i * 128];
    red[g][c] = s;
    __syncthreads();
    if (tid < 128)
        gap[tid] = ((red[0][tid] + red[1][tid]) + (red[2][tid] + red[3][tid])) * (1.f / PIXPB);
    __syncthreads();
    if (tid < 128) {
        float a = bse[tid];
        #pragma unroll 4
        for (int k = 0; k < 128; ++k) a += gap[k] * wse[k * 128 + tid];
        g_att[b * 128 + tid] = a;
    }
}

// =====================================================================
// kB: 128 thr, 4 warps x 32 rows. cp.async(g_s, x) -> att in place ->
//     mma(w2) -> xm + LN2 -> mma(wf1, 2 passes) -> gate -> mma(wf2 LDG) -> out
// =====================================================================
#define KB_XM    38912
#define KB_FWF1  (KB_XM + 67584)
#define KB_FW2   (KB_FWF1 + 65536)
#define KB_E2    (KB_FW2 + 32768)
#define KB_ELN   (KB_E2 + 1024)
#define KB_EBF1  (KB_ELN + 1024)
#define KB_EGAM  (KB_EBF1 + 1024)
#define KB_SMEM  (KB_EGAM + 1024)

__global__ void __launch_bounds__(128, 1)
kB_ffn(const float* __restrict__ x,
       const float* __restrict__ b2,   const float* __restrict__ beta,
       const float* __restrict__ ln2s, const float* __restrict__ ln2b,
       const float* __restrict__ bf1,  const float* __restrict__ bf2,
       const float* __restrict__ gamma, float* __restrict__ out)
{
    extern __shared__ char sm[];
    const int tid = threadIdx.x, lane = tid & 31, warp = tid >> 5;
    const int q = lane & 3, r = lane >> 2, m0 = warp * 32;
    const uint32_t sm_base = smem_u32(sm);

    {
        uint4* d1 = (uint4*)(sm + KB_FWF1);
        const uint4* s1p = (const uint4*)g_fwf1;
        for (int i = tid; i < 4096; i += 128) d1[i] = s1p[i];
        uint4* d2 = (uint4*)(sm + KB_FW2);
        const uint4* s2p = (const uint4*)g_fw2;
        for (int i = tid; i < 2048; i += 128) d2[i] = s2p[i];
        float be = beta[tid], ga = gamma[tid];
        ((float2*)(sm + KB_E2  ))[tid] = make_float2(be, be * b2[tid]);
        ((float2*)(sm + KB_ELN ))[tid] = make_float2(ln2s[tid], ln2b[tid]);
        ((float2*)(sm + KB_EGAM))[tid] = make_float2(ga, ga * bf2[tid]);
        int n = tid, o = (n >> 1) + (n & 1) * 128;
        ((float*)(sm + KB_EBF1))[n] = bf1[o];
        n = tid + 128; o = (n >> 1) + (n & 1) * 128;
        ((float*)(sm + KB_EBF1))[n] = bf1[o];
    }
    __syncthreads();

    const float2* e2p  = (const float2*)(sm + KB_E2);
    const float2* elnp = (const float2*)(sm + KB_ELN);
    const float*  ebfp = (const float*)(sm + KB_EBF1);
    const float2* egap = (const float2*)(sm + KB_EGAM);
    float* xms = (float*)(sm + KB_XM);

    for (int tile = blockIdx.x; tile < NT; tile += GRID_B) {
        const int batch = tile / TPB;

        // ---- cp.async group A: g_s rows m0..m0+31 -> atile ----
        {
            const char* sg = (const char*)(g_s + ((size_t)(tile * 128 + m0)) * 64);
            #pragma unroll
            for (int i = 0; i < 16; ++i) {
                int u = i * 32 + lane, row = u >> 4, ch = u & 15;
                uint32_t dst = sm_base + (uint32_t)(m0 + row) * SA + ch * 16;
                CP_ASYNC16(dst, sg + (size_t)row * 256 + ch * 16);
            }
            CP_COMMIT();
        }
        // ---- cp.async group B: x rows -> xm region ----
        {
            const float* xg = x + ((size_t)(tile * 128 + m0)) * 128;
            #pragma unroll
            for (int i = 0; i < 32; ++i) {
                int u = i * 32 + lane, row = u >> 5, c16 = u & 31;
                uint32_t dst = sm_base + KB_XM + (uint32_t)(m0 + row) * 528 + c16 * 16;
                CP_ASYNC16(dst, xg + (size_t)row * 128 + c16 * 4);
            }
            CP_COMMIT();
        }
        CP_WAIT1();
        __syncwarp();

        // ---- att multiply in place (thread = row tid) ----
        {
            const float4* attr = (const float4*)(g_att + batch * 128);
            char* rowb = sm + tid * SA;
            #pragma unroll
            for (int j = 0; j < 16; ++j) {
                uint4 v = *(uint4*)(rowb + j * 16);
                float4 aA = attr[2*j], aB = attr[2*j+1];
                float2 v0 = unpack_bf2(v.x), v1 = unpack_bf2(v.y);
                float2 v2 = unpack_bf2(v.z), v3 = unpack_bf2(v.w);
                uint4 o;
                o.x = pack_bf2(v0.x * aA.x, v0.y * aA.y);
                o.y = pack_bf2(v1.x * aA.z, v1.y * aA.w);
                o.z = pack_bf2(v2.x * aB.x, v2.y * aB.y);
                o.w = pack_bf2(v3.x * aB.z, v3.y * aB.w);
                *(uint4*)(rowb + j * 16) = o;
            }
        }
        __syncwarp();

        const char* arA = sm + (m0 + r) * SA;
        const char* arB = arA + 16 * SA;

        // ---- GEMM w2 (n128, 2 row-tiles) ----
        float acc[2][16][4];
        #pragma unroll
        for (int t = 0; t < 2; ++t)
            #pragma unroll
            for (int nb = 0; nb < 16; ++nb)
                { acc[t][nb][0]=0.f; acc[t][nb][1]=0.f; acc[t][nb][2]=0.f; acc[t][nb][3]=0.f; }
        #pragma unroll 1
        for (int ks = 0; ks < 8; ++ks) {
            int kb = 32 * ks + 4 * q;
            uint32_t a00 = *(const uint32_t*)(arA + kb);
            uint32_t a01 = *(const uint32_t*)(arA + 8 * SA + kb);
            uint32_t a02 = *(const uint32_t*)(arA + kb + 16);
            uint32_t a03 = *(const uint32_t*)(arA + 8 * SA + kb + 16);
            uint32_t a10 = *(const uint32_t*)(arB + kb);
            uint32_t a11 = *(const uint32_t*)(arB + 8 * SA + kb);
            uint32_t a12 = *(const uint32_t*)(arB + kb + 16);
            uint32_t a13 = *(const uint32_t*)(arB + 8 * SA + kb + 16);
            const uint2* fb = (const uint2*)(sm + KB_FW2) + ks * 512 + lane;
            #pragma unroll
            for (int nb = 0; nb < 16; ++nb) {
                uint2 b = fb[nb * 32];
                mma_bf16(acc[0][nb], a00, a01, a02, a03, b.x, b.y);
                mma_bf16(acc[1][nb], a10, a11, a12, a13, b.x, b.y);
            }
        }

        // ---- xm = x + beta*(d+b2); stats for 4 rows ----
        CP_WAIT0();
        __syncwarp();
        float st1[4] = {0.f,0.f,0.f,0.f}, st2[4] = {0.f,0.f,0.f,0.f};
        #pragma unroll
        for (int t = 0; t < 2; ++t) {
            #pragma unroll
            for (int nb = 0; nb < 16; ++nb) {
                int n0 = 8 * nb + 2 * q;
                float2 e0 = e2p[n0], e1 = e2p[n0 + 1];
                float* pa = xms + (m0 + 16*t + r) * 132 + n0;
                float* pb = pa + 8 * 132;
                float2 xa = *(float2*)pa;
                float2 xb = *(float2*)pb;
                float m00 = xa.x + acc[t][nb][0]*e0.x + e0.y;
                float m01 = xa.y + acc[t][nb][1]*e1.x + e1.y;
                float m10 = xb.x + acc[t][nb][2]*e0.x + e0.y;
                float m11 = xb.y + acc[t][nb][3]*e1.x + e1.y;
                *(float2*)pa = make_float2(m00, m01);
                *(float2*)pb = make_float2(m10, m11);
                st1[2*t]   += m00 + m01; st2[2*t]   += m00*m00 + m01*m01;
                st1[2*t+1] += m10 + m11; st2[2*t+1] += m10*m10 + m11*m11;
            }
        }
        float mu[4], rsx[4];
        #pragma unroll
        for (int i = 0; i < 4; ++i) {
            st1[i] += __shfl_xor_sync(0xffffffffu, st1[i], 1);
            st1[i] += __shfl_xor_sync(0xffffffffu, st1[i], 2);
            st2[i] += __shfl_xor_sync(0xffffffffu, st2[i], 1);
            st2[i] += __shfl_xor_sync(0xffffffffu, st2[i], 2);
            mu[i]  = st1[i] * (1.f/128.f);
            rsx[i] = rsqrtf(fmaxf(st2[i] * (1.f/128.f) - mu[i]*mu[i], 0.f) + EPS);
        }

        // ---- A2 = LN2(xm) -> atile bf16 ----
        #pragma unroll
        for (int t = 0; t < 2; ++t) {
            #pragma unroll
            for (int nb = 0; nb < 16; ++nb) {
                int n0 = 8 * nb + 2 * q;
                float2 p0 = elnp[n0], p1 = elnp[n0 + 1];
                float2 va = *(const float2*)(xms + (m0 + 16*t + r) * 132 + n0);
                float2 vb = *(const float2*)(xms + (m0 + 16*t + r + 8) * 132 + n0);
                *(uint32_t*)(sm + (m0 + 16*t + r)     * SA + n0 * 2) =
                    pack_bf2((va.x-mu[2*t])*rsx[2*t]*p0.x+p0.y, (va.y-mu[2*t])*rsx[2*t]*p1.x+p1.y);
                *(uint32_t*)(sm + (m0 + 16*t + r + 8) * SA + n0 * 2) =
                    pack_bf2((vb.x-mu[2*t+1])*rsx[2*t+1]*p0.x+p0.y, (vb.y-mu[2*t+1])*rsx[2*t+1]*p1.x+p1.y);
            }
        }
        __syncwarp();

        // ---- GEMM wf1 (paired, 2 x n128 passes) ----
        uint32_t gs0[2][16];
        #pragma unroll 1
        for (int half = 0; half < 2; ++half) {
            float acc2[2][16][4];
            #pragma unroll
            for (int t = 0; t < 2; ++t)
                #pragma unroll
                for (int nb = 0; nb < 16; ++nb)
                    { acc2[t][nb][0]=0.f; acc2[t][nb][1]=0.f; acc2[t][nb][2]=0.f; acc2[t][nb][3]=0.f; }
            #pragma unroll 1
            for (int ks = 0; ks < 8; ++ks) {
                int kb = 32 * ks + 4 * q;
                uint32_t a00 = *(const uint32_t*)(arA + kb);
                uint32_t a01 = *(const uint32_t*)(arA + 8 * SA + kb);
                uint32_t a02 = *(const uint32_t*)(arA + kb + 16);
                uint32_t a03 = *(const uint32_t*)(arA + 8 * SA + kb + 16);
                uint32_t a10 = *(const uint32_t*)(arB + kb);
                uint32_t a11 = *(const uint32_t*)(arB + 8 * SA + kb);
                uint32_t a12 = *(const uint32_t*)(arB + kb + 16);
                uint32_t a13 = *(const uint32_t*)(arB + 8 * SA + kb + 16);
                const uint2* fb = (const uint2*)(sm + KB_FWF1) + ks * 1024 + half * 512 + lane;
                #pragma unroll
                for (int nb = 0; nb < 16; ++nb) {
                    uint2 b = fb[nb * 32];
                    mma_bf16(acc2[0][nb], a00, a01, a02, a03, b.x, b.y);
                    mma_bf16(acc2[1][nb], a10, a11, a12, a13, b.x, b.y);
                }
            }
            #pragma unroll
            for (int nb = 0; nb < 16; ++nb) {
                int nbg = half * 16 + nb;
                int n0 = 8 * nbg + 2 * q, j = 4 * nbg + q;
                float e0 = ebfp[n0], e1 = ebfp[n0 + 1];
                float lo0 = (acc2[0][nb][0] + e0) * (acc2[0][nb][1] + e1);
                float hi0 = (acc2[0][nb][2] + e0) * (acc2[0][nb][3] + e1);
                float lo1 = (acc2[1][nb][0] + e0) * (acc2[1][nb][1] + e1);
                float hi1 = (acc2[1][nb][2] + e0) * (acc2[1][nb][3] + e1);
                if (half == 0) {
                    gs0[0][nb] = pack_bf2(lo0, hi0);
                    gs0[1][nb] = pack_bf2(lo1, hi1);
                } else {
                    *(__nv_bfloat16*)(sm + (m0 + r)      * SA + j * 2) = __float2bfloat16(lo0);
                    *(__nv_bfloat16*)(sm + (m0 + r + 8)  * SA + j * 2) = __float2bfloat16(hi0);
                    *(__nv_bfloat16*)(sm + (m0 + r + 16) * SA + j * 2) = __float2bfloat16(lo1);
                    *(__nv_bfloat16*)(sm + (m0 + r + 24) * SA + j * 2) = __float2bfloat16(hi1);
                }
            }
            __syncwarp();
        }
        #pragma unroll
        for (int nb = 0; nb < 16; ++nb) {
            int j = 4 * nb + q;
            float2 v0 = unpack_bf2(gs0[0][nb]);
            float2 v1 = unpack_bf2(gs0[1][nb]);
            *(__nv_bfloat16*)(sm + (m0 + r)      * SA + j * 2) = __float2bfloat16(v0.x);
            *(__nv_bfloat16*)(sm + (m0 + r + 8)  * SA + j * 2) = __float2bfloat16(v0.y);
            *(__nv_bfloat16*)(sm + (m0 + r + 16) * SA + j * 2) = __float2bfloat16(v1.x);
            *(__nv_bfloat16*)(sm + (m0 + r + 24) * SA + j * 2) = __float2bfloat16(v1.y);
        }
        __syncwarp();

        // ---- GEMM wf2 (n128), frags via LDG.64 ----
        float acc3[2][16][4];
        #pragma unroll
        for (int t = 0; t < 2; ++t)
            #pragma unroll
            for (int nb = 0; nb < 16; ++nb)
                { acc3[t][nb][0]=0.f; acc3[t][nb][1]=0.f; acc3[t][nb][2]=0.f; acc3[t][nb][3]=0.f; }
        #pragma unroll 1
        for (int ks = 0; ks < 8; ++ks) {
            int kb = 32 * ks + 4 * q;
            uint32_t a00 = *(const uint32_t*)(arA + kb);
            uint32_t a01 = *(const uint32_t*)(arA + 8 * SA + kb);
            uint32_t a02 = *(const uint32_t*)(arA + kb + 16);
            uint32_t a03 = *(const uint32_t*)(arA + 8 * SA + kb + 16);
            uint32_t a10 = *(const uint32_t*)(arB + kb);
            uint32_t a11 = *(const uint32_t*)(arB + 8 * SA + kb);
            uint32_t a12 = *(const uint32_t*)(arB + kb + 16);
            uint32_t a13 = *(const uint32_t*)(arB + 8 * SA + kb + 16);
            const uint2* fb = (const uint2*)g_fwf2 + ks * 512 + lane;
            #pragma unroll
            for (int nb = 0; nb < 16; ++nb) {
                uint2 b = __ldg(fb + nb * 32);
                mma_bf16(acc3[0][nb], a00, a01, a02, a03, b.x, b.y);
                mma_bf16(acc3[1][nb], a10, a11, a12, a13, b.x, b.y);
            }
        }

        // ---- out = xm + gamma*(d+bf2) ----
        #pragma unroll
        for (int t = 0; t < 2; ++t) {
            float* or0 = out + ((size_t)(tile * 128 + m0 + 16*t + r)) * 128;
            float* or8 = or0 + (size_t)8 * 128;
            #pragma unroll
            for (int nb = 0; nb < 16; ++nb) {
                int n0 = 8 * nb + 2 * q;
                float2 g0 = egap[n0], g1 = egap[n0 + 1];
                float2 va = *(const float2*)(xms + (m0 + 16*t + r)     * 132 + n0);
                float2 vb = *(const float2*)(xms + (m0 + 16*t + r + 8) * 132 + n0);
                *(float2*)(or0 + n0) = make_float2(va.x + acc3[t][nb][0]*g0.x + g0.y,
                                                   va.y + acc3[t][nb][1]*g1.x + g1.y);
                *(float2*)(or8 + n0) = make_float2(vb.x + acc3[t][nb][2]*g0.x + g0.y,
                                                   vb.y + acc3[t][nb][3]*g1.x + g1.y);
            }
        }
        __syncwarp();
    }
}

// =====================================================================
// launch
// =====================================================================
extern "C" void kernel_launch(void* const* d_in, const int* in_sizes, int n_in,
                              void* d_out, int out_size)
{
    (void)in_sizes; (void)n_in; (void)out_size;
    const float* x     = (const float*)d_in[0];
    const float* ln1s  = (const float*)d_in[1];
    const float* ln1b  = (const float*)d_in[2];
    const float* w1    = (const float*)d_in[3];
    const float* b1    = (const float*)d_in[4];
    const float* wdw   = (const float*)d_in[5];
    const float* bdw   = (const float*)d_in[6];
    const float* wse   = (const float*)d_in[7];
    const float* bse   = (const float*)d_in[8];
    const float* w2    = (const float*)d_in[9];
    const float* b2    = (const float*)d_in[10];
    const float* ln2s  = (const float*)d_in[11];
    const float* ln2b  = (const float*)d_in[12];
    const float* wf1   = (const float*)d_in[13];
    const float* bf1   = (const float*)d_in[14];
    const float* wf2   = (const float*)d_in[15];
    const float* bf2   = (const float*)d_in[16];
    const float* beta  = (const float*)d_in[17];
    const float* gamma = (const float*)d_in[18];
    float* out = (float*)d_out;

    cudaFuncSetAttribute(kA_spatial, cudaFuncAttributeMaxDynamicSharedMemorySize, KA_SMEM);
    cudaFuncSetAttribute(kB_ffn,     cudaFuncAttributeMaxDynamicSharedMemorySize, KB_SMEM);

    k0_frags<<<64, 256>>>(w1, w2, wf1, wf2);
    kA_spatial<<<GRID_A, 128, KA_SMEM>>>(x, ln1s, ln1b, b1, wdw, bdw);
    k2_se<<<B_, 512>>>(wse, bse);
    kB_ffn<<<GRID_B, 128, KB_SMEM>>>(x, b2, beta, ln2s, ln2b, bf1, bf2, gamma, out);
}

// round 9
// speedup vs baseline: 1.0349x; 1.0349x over previous
#include <cuda_runtime.h>
#include <cuda_bf16.h>
#include <cstdint>

#define B_     8
#define C_     128
#define PIXPB  36864
#define NPIX   294912
#define NT     2304             // 128-pixel tiles
#define TPB    288              // tiles per batch
#define EPS    1e-6f
#define GRID_A 296
#define GRID_B 148
#define SA     304              // A-tile row stride bytes (conflict-free)

// ---------------- device globals (no allocation) ----------------
__device__ uint32_t g_s[(size_t)NPIX * 64];   // gated branch bf16x2 [pix][64]
__device__ float    g_gpart[NT * 128];        // per-tile GAP partials
__device__ float    g_g2[8 * 9 * 128];        // stage-1 reduced partials
__device__ float    g_att[B_ * C_];
// mma.sync B-fragment images: [ks][nb][lane][e] uint32 (bf16x2) -> uint2 per lane
__device__ uint32_t g_fw1 [8 * 32 * 32 * 2];  // w1  (pair-permuted), N=256
__device__ uint32_t g_fwf1[8 * 32 * 32 * 2];  // wf1 (pair-permuted), N=256
__device__ uint32_t g_fw2 [8 * 16 * 32 * 2];  // w2, N=128
__device__ uint32_t g_fwf2[8 * 16 * 32 * 2];  // wf2, N=128

__device__ __forceinline__ uint32_t pack_bf2(float a, float b) {
    __nv_bfloat162 h = __floats2bfloat162_rn(a, b);   // low = a
    return *reinterpret_cast<uint32_t*>(&h);
}
__device__ __forceinline__ float2 unpack_bf2(uint32_t w) {
    __nv_bfloat162 h = *reinterpret_cast<const __nv_bfloat162*>(&w);
    return make_float2(__low2float(h), __high2float(h));
}
__device__ __forceinline__ void mma_bf16(float* c, uint32_t a0, uint32_t a1,
                                         uint32_t a2, uint32_t a3,
                                         uint32_t b0, uint32_t b1) {
    asm volatile(
        "mma.sync.aligned.m16n8k16.row.col.f32.bf16.bf16.f32 "
        "{%0,%1,%2,%3}, {%4,%5,%6,%7}, {%8,%9}, {%0,%1,%2,%3};\n"
        : "+f"(c[0]), "+f"(c[1]), "+f"(c[2]), "+f"(c[3])
        : "r"(a0), "r"(a1), "r"(a2), "r"(a3), "r"(b0), "r"(b1));
}
__device__ __forceinline__ uint32_t smem_u32(const void* p) {
    uint32_t a;
    asm("{ .reg .u64 t; cvta.to.shared.u64 t, %1; cvt.u32.u64 %0, t; }" : "=r"(a) : "l"(p));
    return a;
}
#define CP_ASYNC16(dst, src) \
    asm volatile("cp.async.ca.shared.global [%0], [%1], 16;" :: "r"(dst), "l"(src))
#define CP_COMMIT()  asm volatile("cp.async.commit_group;" ::: "memory")
#define CP_WAIT1()   asm volatile("cp.async.wait_group 1;" ::: "memory")
#define CP_WAIT0()   asm volatile("cp.async.wait_group 0;" ::: "memory")

// =====================================================================
// k0: B-fragment images, [ks][nb][lane][e] so (b0,b1) is one uint2.
// =====================================================================
__global__ void k0_frags(const float* __restrict__ w1, const float* __restrict__ w2,
                         const float* __restrict__ wf1, const float* __restrict__ wf2)
{
    int i0 = blockIdx.x * blockDim.x + threadIdx.x, str = gridDim.x * blockDim.x;
    for (int i = i0; i < 8 * 32 * 32 * 2; i += str) {
        int e = i & 1, lane = (i >> 1) & 31, nb = (i >> 6) & 31, ks = i >> 11;
        int n = 8 * nb + (lane >> 2);
        int k = 16 * ks + 2 * (lane & 3) + 8 * e;
        int o = (n >> 1) + (n & 1) * 128;
        g_fw1 [i] = pack_bf2(w1 [k * 256 + o], w1 [(k + 1) * 256 + o]);
        g_fwf1[i] = pack_bf2(wf1[k * 256 + o], wf1[(k + 1) * 256 + o]);
    }
    for (int i = i0; i < 8 * 16 * 32 * 2; i += str) {
        int e = i & 1, lane = (i >> 1) & 31, nb = (i >> 6) & 15, ks = i >> 10;
        int n = 8 * nb + (lane >> 2);
        int k = 16 * ks + 2 * (lane & 3) + 8 * e;
        g_fw2 [i] = pack_bf2(w2 [k * 128 + n], w2 [(k + 1) * 128 + n]);
        g_fwf2[i] = pack_bf2(wf2[k * 128 + n], wf2[(k + 1) * 128 + n]);
    }
}

// =====================================================================
// kA: 256 thr, 8 warps x 16 rows, 2 CTAs/SM. LN1 -> mma(w1, 2 x n128)
//     -> dw-affine + gate -> g_s + per-tile GAP.
// =====================================================================
#define KA_FW1  38912
#define KA_EW   (KA_FW1 + 65536)
#define KA_LN   (KA_EW + 2048)
#define KA_GAP  (KA_LN + 1024)
#define KA_SMEM (KA_GAP + 4096)   // 111616

__global__ void __launch_bounds__(256, 2)
kA_spatial(const float* __restrict__ x,
           const float* __restrict__ ln1s, const float* __restrict__ ln1b,
           const float* __restrict__ b1,   const float* __restrict__ wdw,
           const float* __restrict__ bdw)
{
    extern __shared__ char sm[];
    const int tid = threadIdx.x, lane = tid & 31, warp = tid >> 5;
    const int q = lane & 3, r = lane >> 2, m0 = warp * 16;

    {
        uint4* dst = (uint4*)(sm + KA_FW1);
        const uint4* src = (const uint4*)g_fw1;
        for (int i = tid; i < 4096; i += 256) dst[i] = src[i];
        if (tid < 256) {
            int n = tid, o = (n >> 1) + (n & 1) * 128;
            float w = wdw[o];
            ((float2*)(sm + KA_EW))[n] = make_float2(w, b1[o] * w + bdw[o]);
        }
        if (tid < 128)
            ((float2*)(sm + KA_LN))[tid] = make_float2(ln1s[tid], ln1b[tid]);
    }
    __syncthreads();

    const float2* ewp = (const float2*)(sm + KA_EW);
    const float2* lnp = (const float2*)(sm + KA_LN);
    float* gapw = (float*)(sm + KA_GAP);
    const int pl = tid >> 1, h = tid & 1;

    for (int tile = blockIdx.x; tile < NT; tile += GRID_A) {
        // ---- LN1: thread = (pixel pl, channel half h) ----
        const float4* xr = (const float4*)x + ((size_t)(tile * 128 + pl)) * 32 + h * 16;
        float4 xv[16];
        float s1 = 0.f, s2 = 0.f;
        #pragma unroll
        for (int i = 0; i < 16; ++i) {
            xv[i] = xr[i];
            s1 += xv[i].x + xv[i].y + xv[i].z + xv[i].w;
            s2 += xv[i].x*xv[i].x + xv[i].y*xv[i].y + xv[i].z*xv[i].z + xv[i].w*xv[i].w;
        }
        s1 += __shfl_xor_sync(0xffffffffu, s1, 1);
        s2 += __shfl_xor_sync(0xffffffffu, s2, 1);
        const float mu = s1 * (1.f/128.f);
        const float rs = rsqrtf(fmaxf(s2 * (1.f/128.f) - mu*mu, 0.f) + EPS);

        char* rowb = sm + pl * SA + h * 128;
        #pragma unroll
        for (int j = 0; j < 8; ++j) {
            float4 v0 = xv[2*j], v1 = xv[2*j+1];
            int c = h * 64 + 8 * j;
            float2 p0 = lnp[c],   p1 = lnp[c+1], p2 = lnp[c+2], p3 = lnp[c+3];
            float2 p4 = lnp[c+4], p5 = lnp[c+5], p6 = lnp[c+6], p7 = lnp[c+7];
            uint4 o;
            o.x = pack_bf2((v0.x-mu)*rs*p0.x+p0.y, (v0.y-mu)*rs*p1.x+p1.y);
            o.y = pack_bf2((v0.z-mu)*rs*p2.x+p2.y, (v0.w-mu)*rs*p3.x+p3.y);
            o.z = pack_bf2((v1.x-mu)*rs*p4.x+p4.y, (v1.y-mu)*rs*p5.x+p5.y);
            o.w = pack_bf2((v1.z-mu)*rs*p6.x+p6.y, (v1.w-mu)*rs*p7.x+p7.y);
            *(uint4*)(rowb + j * 16) = o;
        }
        __syncwarp();

        const char* ar0 = sm + (m0 + r) * SA;
        uint32_t gsave[16];

        #pragma unroll 1
        for (int half = 0; half < 2; ++half) {
            float acc[16][4];
            #pragma unroll
            for (int nb = 0; nb < 16; ++nb)
                { acc[nb][0]=0.f; acc[nb][1]=0.f; acc[nb][2]=0.f; acc[nb][3]=0.f; }

            #pragma unroll 1
            for (int ks = 0; ks < 8; ++ks) {
                int kb = 32 * ks + 4 * q;
                uint32_t a0 = *(const uint32_t*)(ar0 + kb);
                uint32_t a1 = *(const uint32_t*)(ar0 + 8 * SA + kb);
                uint32_t a2 = *(const uint32_t*)(ar0 + kb + 16);
                uint32_t a3 = *(const uint32_t*)(ar0 + 8 * SA + kb + 16);
                const uint2* fb = (const uint2*)(sm + KA_FW1) + ks * 1024 + half * 512 + lane;
                #pragma unroll
                for (int nb = 0; nb < 16; ++nb) {
                    uint2 b = fb[nb * 32];
                    mma_bf16(acc[nb], a0, a1, a2, a3, b.x, b.y);
                }
            }

            #pragma unroll
            for (int nb = 0; nb < 16; ++nb) {
                int nbg = half * 16 + nb;
                int n0 = 8 * nbg + 2 * q, j = 4 * nbg + q;
                float2 e0 = ewp[n0], e1 = ewp[n0 + 1];
                float lo = (acc[nb][0]*e0.x + e0.y) * (acc[nb][1]*e1.x + e1.y);
                float hi = (acc[nb][2]*e0.x + e0.y) * (acc[nb][3]*e1.x + e1.y);
                float g = lo + hi;
                g += __shfl_xor_sync(0xffffffffu, g, 4);
                g += __shfl_xor_sync(0xffffffffu, g, 8);
                g += __shfl_xor_sync(0xffffffffu, g, 16);
                if (r == 0) gapw[warp * 128 + j] = g;
                if (half == 0) {
                    gsave[nb] = pack_bf2(lo, hi);
                } else {
                    *(__nv_bfloat16*)(sm + (m0 + r)     * SA + j * 2) = __float2bfloat16(lo);
                    *(__nv_bfloat16*)(sm + (m0 + r + 8) * SA + j * 2) = __float2bfloat16(hi);
                }
            }
            __syncwarp();
        }
        #pragma unroll
        for (int nb = 0; nb < 16; ++nb) {
            int j = 4 * nb + q;
            float2 v = unpack_bf2(gsave[nb]);
            *(__nv_bfloat16*)(sm + (m0 + r)     * SA + j * 2) = __float2bfloat16(v.x);
            *(__nv_bfloat16*)(sm + (m0 + r + 8) * SA + j * 2) = __float2bfloat16(v.y);
        }
        __syncwarp();

        // ---- coalesced copy to g_s ----
        #pragma unroll
        for (int i = 0; i < 8; ++i) {
            int u = lane + 32 * i, row = u >> 4, ch = u & 15;
            uint4 v = *(const uint4*)(sm + (m0 + row) * SA + ch * 16);
            ((uint4*)g_s)[((size_t)(tile * 128 + m0 + row)) * 16 + ch] = v;
        }

        // ---- GAP partial: sum 8 warps in fixed order ----
        __syncthreads();
        if (tid < 128) {
            float s = 0.f;
            #pragma unroll
            for (int w = 0; w < 8; ++w) s += gapw[w * 128 + tid];
            g_gpart[tile * 128 + tid] = s;
        }
        __syncthreads();
    }
}

// =====================================================================
// k2_red: stage-1 reduce — 72 blocks, each sums 32 consecutive tiles
// =====================================================================
__global__ void k2_red()
{
    const int blk = blockIdx.x, c = threadIdx.x;      // blk = b*9 + g
    const float* src = g_gpart + (size_t)(blk * 32) * 128 + c;
    float s = 0.f;
    #pragma unroll 8
    for (int i = 0; i < 32; ++i) s += src[(size_t)i * 128];
    g_g2[blk * 128 + c] = s;
}

// =====================================================================
// k2_se: sum 9 group-partials per batch + SE dense
// =====================================================================
__global__ void k2_se(const float* __restrict__ wse, const float* __restrict__ bse)
{
    __shared__ float gap[128];
    const int b = blockIdx.x, j = threadIdx.x;
    float s = 0.f;
    #pragma unroll
    for (int g = 0; g < 9; ++g) s += g_g2[(b * 9 + g) * 128 + j];
    gap[j] = s * (1.f / PIXPB);
    __syncthreads();
    float a = bse[j];
    #pragma unroll 4
    for (int k = 0; k < 128; ++k) a += gap[k] * wse[k * 128 + j];
    g_att[b * 128 + j] = a;
}

// =====================================================================
// kB: 256 thr, 8 warps x 16 rows. cp.async(g_s, x) -> att -> mma(w2)
//     -> xm + LN2 -> mma(wf1, 2 x n128) -> gate -> mma(wf2 LDG) -> out
// =====================================================================
#define KB_XM    38912
#define KB_FWF1  (KB_XM + 67584)
#define KB_FW2   (KB_FWF1 + 65536)
#define KB_E2    (KB_FW2 + 32768)
#define KB_ELN   (KB_E2 + 1024)
#define KB_EBF1  (KB_ELN + 1024)
#define KB_EGAM  (KB_EBF1 + 1024)
#define KB_SMEM  (KB_EGAM + 1024)

__global__ void __launch_bounds__(256, 1)
kB_ffn(const float* __restrict__ x,
       const float* __restrict__ b2,   const float* __restrict__ beta,
       const float* __restrict__ ln2s, const float* __restrict__ ln2b,
       const float* __restrict__ bf1,  const float* __restrict__ bf2,
       const float* __restrict__ gamma, float* __restrict__ out)
{
    extern __shared__ char sm[];
    const int tid = threadIdx.x, lane = tid & 31, warp = tid >> 5;
    const int q = lane & 3, r = lane >> 2, m0 = warp * 16;
    const uint32_t sm_base = smem_u32(sm);

    {
        uint4* d1 = (uint4*)(sm + KB_FWF1);
        const uint4* s1p = (const uint4*)g_fwf1;
        for (int i = tid; i < 4096; i += 256) d1[i] = s1p[i];
        uint4* d2 = (uint4*)(sm + KB_FW2);
        const uint4* s2p = (const uint4*)g_fw2;
        for (int i = tid; i < 2048; i += 256) d2[i] = s2p[i];
        if (tid < 128) {
            float be = beta[tid], ga = gamma[tid];
            ((float2*)(sm + KB_E2  ))[tid] = make_float2(be, be * b2[tid]);
            ((float2*)(sm + KB_ELN ))[tid] = make_float2(ln2s[tid], ln2b[tid]);
            ((float2*)(sm + KB_EGAM))[tid] = make_float2(ga, ga * bf2[tid]);
        }
        if (tid < 256) {
            int n = tid, o = (n >> 1) + (n & 1) * 128;
            ((float*)(sm + KB_EBF1))[n] = bf1[o];
        }
    }
    __syncthreads();

    const float2* e2p  = (const float2*)(sm + KB_E2);
    const float2* elnp = (const float2*)(sm + KB_ELN);
    const float*  ebfp = (const float*)(sm + KB_EBF1);
    const float2* egap = (const float2*)(sm + KB_EGAM);
    float* xms = (float*)(sm + KB_XM);
    const int pl = tid >> 1, h = tid & 1;

    for (int tile = blockIdx.x; tile < NT; tile += GRID_B) {
        const int batch = tile / TPB;

        // ---- cp.async group A: g_s half-row -> atile ----
        {
            const char* sg = (const char*)(g_s + ((size_t)(tile * 128 + pl)) * 64) + h * 128;
            uint32_t dst = sm_base + (uint32_t)pl * SA + h * 128;
            #pragma unroll
            for (int j = 0; j < 8; ++j)
                CP_ASYNC16(dst + j * 16, sg + j * 16);
            CP_COMMIT();
        }
        // ---- cp.async group B: x rows -> xm region ----
        {
            const float* xg = x + ((size_t)(tile * 128 + m0)) * 128;
            #pragma unroll
            for (int i = 0; i < 16; ++i) {
                int gidx = i * 32 + lane;
                int row = gidx >> 5, c16 = gidx & 31;
                uint32_t dst = sm_base + KB_XM + (uint32_t)(m0 + row) * 528 + c16 * 16;
                CP_ASYNC16(dst, xg + (size_t)row * 128 + c16 * 4);
            }
            CP_COMMIT();
        }
        CP_WAIT1();
        __syncwarp();

        // ---- att multiply in place (thread = row pl, half h) ----
        {
            const float4* attr = (const float4*)(g_att + batch * 128 + h * 64);
            char* rowb = sm + pl * SA + h * 128;
            #pragma unroll
            for (int j = 0; j < 8; ++j) {
                uint4 v = *(uint4*)(rowb + j * 16);
                float4 aA = attr[2*j], aB = attr[2*j+1];
                float2 v0 = unpack_bf2(v.x), v1 = unpack_bf2(v.y);
                float2 v2 = unpack_bf2(v.z), v3 = unpack_bf2(v.w);
                uint4 o;
                o.x = pack_bf2(v0.x * aA.x, v0.y * aA.y);
                o.y = pack_bf2(v1.x * aA.z, v1.y * aA.w);
                o.z = pack_bf2(v2.x * aB.x, v2.y * aB.y);
                o.w = pack_bf2(v3.x * aB.z, v3.y * aB.w);
                *(uint4*)(rowb + j * 16) = o;
            }
        }
        __syncwarp();

        const char* ar0 = sm + (m0 + r) * SA;

        // ---- GEMM w2 (n128) ----
        float acc[16][4];
        #pragma unroll
        for (int nb = 0; nb < 16; ++nb)
            { acc[nb][0]=0.f; acc[nb][1]=0.f; acc[nb][2]=0.f; acc[nb][3]=0.f; }
        #pragma unroll 1
        for (int ks = 0; ks < 8; ++ks) {
            int kb = 32 * ks + 4 * q;
            uint32_t a0 = *(const uint32_t*)(ar0 + kb);
            uint32_t a1 = *(const uint32_t*)(ar0 + 8 * SA + kb);
            uint32_t a2 = *(const uint32_t*)(ar0 + kb + 16);
            uint32_t a3 = *(const uint32_t*)(ar0 + 8 * SA + kb + 16);
            const uint2* fb = (const uint2*)(sm + KB_FW2) + ks * 512 + lane;
            #pragma unroll
            for (int nb = 0; nb < 16; ++nb) {
                uint2 b = fb[nb * 32];
                mma_bf16(acc[nb], a0, a1, a2, a3, b.x, b.y);
            }
        }

        // ---- xm = x + beta*(d+b2); stash f32; LN2 stats via quad shfl ----
        CP_WAIT0();
        __syncwarp();
        float s1a = 0.f, s2a = 0.f, s1b = 0.f, s2b = 0.f;
        #pragma unroll
        for (int nb = 0; nb < 16; ++nb) {
            int n0 = 8 * nb + 2 * q;
            float2 e0 = e2p[n0], e1 = e2p[n0 + 1];
            float* pa = xms + (m0 + r)     * 132 + n0;
            float* pb = xms + (m0 + r + 8) * 132 + n0;
            float2 xa = *(float2*)pa;
            float2 xb = *(float2*)pb;
            float m00 = xa.x + acc[nb][0]*e0.x + e0.y;
            float m01 = xa.y + acc[nb][1]*e1.x + e1.y;
            float m10 = xb.x + acc[nb][2]*e0.x + e0.y;
            float m11 = xb.y + acc[nb][3]*e1.x + e1.y;
            *(float2*)pa = make_float2(m00, m01);
            *(float2*)pb = make_float2(m10, m11);
            s1a += m00 + m01; s2a += m00*m00 + m01*m01;
            s1b += m10 + m11; s2b += m10*m10 + m11*m11;
        }
        s1a += __shfl_xor_sync(0xffffffffu, s1a, 1); s1a += __shfl_xor_sync(0xffffffffu, s1a, 2);
        s2a += __shfl_xor_sync(0xffffffffu, s2a, 1); s2a += __shfl_xor_sync(0xffffffffu, s2a, 2);
        s1b += __shfl_xor_sync(0xffffffffu, s1b, 1); s1b += __shfl_xor_sync(0xffffffffu, s1b, 2);
        s2b += __shfl_xor_sync(0xffffffffu, s2b, 1); s2b += __shfl_xor_sync(0xffffffffu, s2b, 2);
        const float mua = s1a * (1.f/128.f);
        const float rsa = rsqrtf(fmaxf(s2a * (1.f/128.f) - mua*mua, 0.f) + EPS);
        const float mub = s1b * (1.f/128.f);
        const float rsb = rsqrtf(fmaxf(s2b * (1.f/128.f) - mub*mub, 0.f) + EPS);

        // ---- A2 = LN2(xm) -> atile bf16 ----
        #pragma unroll
        for (int nb = 0; nb < 16; ++nb) {
            int n0 = 8 * nb + 2 * q;
            float2 p0 = elnp[n0], p1 = elnp[n0 + 1];
            float2 va = *(const float2*)(xms + (m0 + r)     * 132 + n0);
            float2 vb = *(const float2*)(xms + (m0 + r + 8) * 132 + n0);
            *(uint32_t*)(sm + (m0 + r)     * SA + n0 * 2) =
                pack_bf2((va.x-mua)*rsa*p0.x+p0.y, (va.y-mua)*rsa*p1.x+p1.y);
            *(uint32_t*)(sm + (m0 + r + 8) * SA + n0 * 2) =
                pack_bf2((vb.x-mub)*rsb*p0.x+p0.y, (vb.y-mub)*rsb*p1.x+p1.y);
        }
        __syncwarp();

        // ---- GEMM wf1 (paired, 2 x n128 passes) ----
        uint32_t gsave[16];
        #pragma unroll 1
        for (int half = 0; half < 2; ++half) {
            float acc2[16][4];
            #pragma unroll
            for (int nb = 0; nb < 16; ++nb)
                { acc2[nb][0]=0.f; acc2[nb][1]=0.f; acc2[nb][2]=0.f; acc2[nb][3]=0.f; }
            #pragma unroll 1
            for (int ks = 0; ks < 8; ++ks) {
                int kb = 32 * ks + 4 * q;
                uint32_t a0 = *(const uint32_t*)(ar0 + kb);
                uint32_t a1 = *(const uint32_t*)(ar0 + 8 * SA + kb);
                uint32_t a2 = *(const uint32_t*)(ar0 + kb + 16);
                uint32_t a3 = *(const uint32_t*)(ar0 + 8 * SA + kb + 16);
                const uint2* fb = (const uint2*)(sm + KB_FWF1) + ks * 1024 + half * 512 + lane;
                #pragma unroll
                for (int nb = 0; nb < 16; ++nb) {
                    uint2 b = fb[nb * 32];
                    mma_bf16(acc2[nb], a0, a1, a2, a3, b.x, b.y);
                }
            }
            #pragma unroll
            for (int nb = 0; nb < 16; ++nb) {
                int nbg = half * 16 + nb;
                int n0 = 8 * nbg + 2 * q, j = 4 * nbg + q;
                float e0 = ebfp[n0], e1 = ebfp[n0 + 1];
                float lo = (acc2[nb][0] + e0) * (acc2[nb][1] + e1);
                float hi = (acc2[nb][2] + e0) * (acc2[nb][3] + e1);
                if (half == 0) {
                    gsave[nb] = pack_bf2(lo, hi);
                } else {
                    *(__nv_bfloat16*)(sm + (m0 + r)     * SA + j * 2) = __float2bfloat16(lo);
                    *(__nv_bfloat16*)(sm + (m0 + r + 8) * SA + j * 2) = __float2bfloat16(hi);
                }
            }
            __syncwarp();
        }
        #pragma unroll
        for (int nb = 0; nb < 16; ++nb) {
            int j = 4 * nb + q;
            float2 v = unpack_bf2(gsave[nb]);
            *(__nv_bfloat16*)(sm + (m0 + r)     * SA + j * 2) = __float2bfloat16(v.x);
            *(__nv_bfloat16*)(sm + (m0 + r + 8) * SA + j * 2) = __float2bfloat16(v.y);
        }
        __syncwarp();

        // ---- GEMM wf2 (n128), frags via LDG.64 ----
        float acc3[16][4];
        #pragma unroll
        for (int nb = 0; nb < 16; ++nb)
            { acc3[nb][0]=0.f; acc3[nb][1]=0.f; acc3[nb][2]=0.f; acc3[nb][3]=0.f; }
        #pragma unroll 1
        for (int ks = 0; ks < 8; ++ks) {
            int kb = 32 * ks + 4 * q;
            uint32_t a0 = *(const uint32_t*)(ar0 + kb);
            uint32_t a1 = *(const uint32_t*)(ar0 + 8 * SA + kb);
            uint32_t a2 = *(const uint32_t*)(ar0 + kb + 16);
            uint32_t a3 = *(const uint32_t*)(ar0 + 8 * SA + kb + 16);
            const uint2* fb = (const uint2*)g_fwf2 + ks * 512 + lane;
            #pragma unroll
            for (int nb = 0; nb < 16; ++nb) {
                uint2 b = __ldg(fb + nb * 32);
                mma_bf16(acc3[nb], a0, a1, a2, a3, b.x, b.y);
            }
        }

        // ---- out = xm + gamma*(d+bf2) ----
        float* or0 = out + ((size_t)(tile * 128 + m0 + r)) * 128;
        float* or8 = or0 + (size_t)8 * 128;
        #pragma unroll
        for (int nb = 0; nb < 16; ++nb) {
            int n0 = 8 * nb + 2 * q;
            float2 g0 = egap[n0], g1 = egap[n0 + 1];
            float2 va = *(const float2*)(xms + (m0 + r)     * 132 + n0);
            float2 vb = *(const float2*)(xms + (m0 + r + 8) * 132 + n0);
            *(float2*)(or0 + n0) = make_float2(va.x + acc3[nb][0]*g0.x + g0.y,
                                               va.y + acc3[nb][1]*g1.x + g1.y);
            *(float2*)(or8 + n0) = make_float2(vb.x + acc3[nb][2]*g0.x + g0.y,
                                               vb.y + acc3[nb][3]*g1.x + g1.y);
        }
        __syncwarp();
    }
}

// =====================================================================
// launch
// =====================================================================
extern "C" void kernel_launch(void* const* d_in, const int* in_sizes, int n_in,
                              void* d_out, int out_size)
{
    (void)in_sizes; (void)n_in; (void)out_size;
    const float* x     = (const float*)d_in[0];
    const float* ln1s  = (const float*)d_in[1];
    const float* ln1b  = (const float*)d_in[2];
    const float* w1    = (const float*)d_in[3];
    const float* b1    = (const float*)d_in[4];
    const float* wdw   = (const float*)d_in[5];
    const float* bdw   = (const float*)d_in[6];
    const float* wse   = (const float*)d_in[7];
    const float* bse   = (const float*)d_in[8];
    const float* w2    = (const float*)d_in[9];
    const float* b2    = (const float*)d_in[10];
    const float* ln2s  = (const float*)d_in[11];
    const float* ln2b  = (const float*)d_in[12];
    const float* wf1   = (const float*)d_in[13];
    const float* bf1   = (const float*)d_in[14];
    const float* wf2   = (const float*)d_in[15];
    const float* bf2   = (const float*)d_in[16];
    const float* beta  = (const float*)d_in[17];
    const float* gamma = (const float*)d_in[18];
    float* out = (float*)d_out;

    cudaFuncSetAttribute(kA_spatial, cudaFuncAttributeMaxDynamicSharedMemorySize, KA_SMEM);
    cudaFuncSetAttribute(kB_ffn,     cudaFuncAttributeMaxDynamicSharedMemorySize, KB_SMEM);

    k0_frags<<<64, 256>>>(w1, w2, wf1, wf2);
    kA_spatial<<<GRID_A, 256, KA_SMEM>>>(x, ln1s, ln1b, b1, wdw, bdw);
    k2_red<<<72, 128>>>();
    k2_se<<<B_, 128>>>(wse, bse);
    kB_ffn<<<GRID_B, 256, KB_SMEM>>>(x, b2, beta, ln2s, ln2b, bf1, bf2, gamma, out);
}

// round 10
// speedup vs baseline: 1.0878x; 1.0512x over previous
#include <cuda_runtime.h>
#include <cuda_bf16.h>
#include <cstdint>

#define B_     8
#define C_     128
#define PIXPB  36864
#define NPIX   294912
#define NT     2304             // 128-pixel tiles
#define TPB    288              // tiles per batch
#define EPS    1e-6f
#define GRID_A 296
#define GRID_B 144              // 18 CTAs per batch x 16 tiles
#define SA     304              // A-tile row stride bytes (conflict-free)

// ---------------- device globals (no allocation) ----------------
__device__ uint32_t g_s[(size_t)NPIX * 64];   // gated branch bf16x2 [pix][64]
__device__ float    g_gpart[NT * 128];        // per-tile GAP partials
__device__ float    g_att[B_ * C_];
// mma.sync B-fragment images: [ks][nb][lane][e] uint32 (bf16x2) -> uint2 per lane
__device__ uint32_t g_fw1 [8 * 32 * 32 * 2];  // w1  (pair-permuted), N=256
__device__ uint32_t g_fwf1[8 * 32 * 32 * 2];  // wf1 (pair-permuted), N=256
__device__ uint32_t g_fw2 [8 * 16 * 32 * 2];  // w2, N=128
__device__ uint32_t g_fwf2[8 * 16 * 32 * 2];  // wf2, N=128

__device__ __forceinline__ uint32_t pack_bf2(float a, float b) {
    __nv_bfloat162 h = __floats2bfloat162_rn(a, b);   // low = a
    return *reinterpret_cast<uint32_t*>(&h);
}
__device__ __forceinline__ float2 unpack_bf2(uint32_t w) {
    __nv_bfloat162 h = *reinterpret_cast<const __nv_bfloat162*>(&w);
    return make_float2(__low2float(h), __high2float(h));
}
__device__ __forceinline__ void mma_bf16(float* c, uint32_t a0, uint32_t a1,
                                         uint32_t a2, uint32_t a3,
                                         uint32_t b0, uint32_t b1) {
    asm volatile(
        "mma.sync.aligned.m16n8k16.row.col.f32.bf16.bf16.f32 "
        "{%0,%1,%2,%3}, {%4,%5,%6,%7}, {%8,%9}, {%0,%1,%2,%3};\n"
        : "+f"(c[0]), "+f"(c[1]), "+f"(c[2]), "+f"(c[3])
        : "r"(a0), "r"(a1), "r"(a2), "r"(a3), "r"(b0), "r"(b1));
}
__device__ __forceinline__ uint32_t smem_u32(const void* p) {
    uint32_t a;
    asm("{ .reg .u64 t; cvta.to.shared.u64 t, %1; cvt.u32.u64 %0, t; }" : "=r"(a) : "l"(p));
    return a;
}
#define CP_ASYNC16(dst, src) \
    asm volatile("cp.async.ca.shared.global [%0], [%1], 16;" :: "r"(dst), "l"(src))
#define CP_COMMIT()  asm volatile("cp.async.commit_group;" ::: "memory")
#define CP_WAIT1()   asm volatile("cp.async.wait_group 1;" ::: "memory")
#define CP_WAIT0()   asm volatile("cp.async.wait_group 0;" ::: "memory")

// =====================================================================
// k0: B-fragment images, [ks][nb][lane][e] so (b0,b1) is one uint2.
// =====================================================================
__global__ void k0_frags(const float* __restrict__ w1, const float* __restrict__ w2,
                         const float* __restrict__ wf1, const float* __restrict__ wf2)
{
    int i0 = blockIdx.x * blockDim.x + threadIdx.x, str = gridDim.x * blockDim.x;
    for (int i = i0; i < 8 * 32 * 32 * 2; i += str) {
        int e = i & 1, lane = (i >> 1) & 31, nb = (i >> 6) & 31, ks = i >> 11;
        int n = 8 * nb + (lane >> 2);
        int k = 16 * ks + 2 * (lane & 3) + 8 * e;
        int o = (n >> 1) + (n & 1) * 128;
        g_fw1 [i] = pack_bf2(w1 [k * 256 + o], w1 [(k + 1) * 256 + o]);
        g_fwf1[i] = pack_bf2(wf1[k * 256 + o], wf1[(k + 1) * 256 + o]);
    }
    for (int i = i0; i < 8 * 16 * 32 * 2; i += str) {
        int e = i & 1, lane = (i >> 1) & 31, nb = (i >> 6) & 15, ks = i >> 10;
        int n = 8 * nb + (lane >> 2);
        int k = 16 * ks + 2 * (lane & 3) + 8 * e;
        g_fw2 [i] = pack_bf2(w2 [k * 128 + n], w2 [(k + 1) * 128 + n]);
        g_fwf2[i] = pack_bf2(wf2[k * 128 + n], wf2[(k + 1) * 128 + n]);
    }
}

// =====================================================================
// kA: 256 thr, 8 warps x 16 rows, 2 CTAs/SM. LN1 -> mma(w1, 2 x n128)
//     -> dw-affine + gate -> g_s + per-tile GAP.
// =====================================================================
#define KA_FW1  38912
#define KA_EW   (KA_FW1 + 65536)
#define KA_LN   (KA_EW + 2048)
#define KA_GAP  (KA_LN + 1024)
#define KA_SMEM (KA_GAP + 4096)   // 111616

__global__ void __launch_bounds__(256, 2)
kA_spatial(const float* __restrict__ x,
           const float* __restrict__ ln1s, const float* __restrict__ ln1b,
           const float* __restrict__ b1,   const float* __restrict__ wdw,
           const float* __restrict__ bdw)
{
    extern __shared__ char sm[];
    const int tid = threadIdx.x, lane = tid & 31, warp = tid >> 5;
    const int q = lane & 3, r = lane >> 2, m0 = warp * 16;

    {
        uint4* dst = (uint4*)(sm + KA_FW1);
        const uint4* src = (const uint4*)g_fw1;
        for (int i = tid; i < 4096; i += 256) dst[i] = src[i];
        if (tid < 256) {
            int n = tid, o = (n >> 1) + (n & 1) * 128;
            float w = wdw[o];
            ((float2*)(sm + KA_EW))[n] = make_float2(w, b1[o] * w + bdw[o]);
        }
        if (tid < 128)
            ((float2*)(sm + KA_LN))[tid] = make_float2(ln1s[tid], ln1b[tid]);
    }
    __syncthreads();

    const float2* ewp = (const float2*)(sm + KA_EW);
    const float2* lnp = (const float2*)(sm + KA_LN);
    float* gapw = (float*)(sm + KA_GAP);
    const int pl = tid >> 1, h = tid & 1;

    for (int tile = blockIdx.x; tile < NT; tile += GRID_A) {
        // ---- LN1: thread = (pixel pl, channel half h) ----
        const float4* xr = (const float4*)x + ((size_t)(tile * 128 + pl)) * 32 + h * 16;
        float4 xv[16];
        float s1 = 0.f, s2 = 0.f;
        #pragma unroll
        for (int i = 0; i < 16; ++i) {
            xv[i] = xr[i];
            s1 += xv[i].x + xv[i].y + xv[i].z + xv[i].w;
            s2 += xv[i].x*xv[i].x + xv[i].y*xv[i].y + xv[i].z*xv[i].z + xv[i].w*xv[i].w;
        }
        s1 += __shfl_xor_sync(0xffffffffu, s1, 1);
        s2 += __shfl_xor_sync(0xffffffffu, s2, 1);
        const float mu = s1 * (1.f/128.f);
        const float rs = rsqrtf(fmaxf(s2 * (1.f/128.f) - mu*mu, 0.f) + EPS);

        char* rowb = sm + pl * SA + h * 128;
        #pragma unroll
        for (int j = 0; j < 8; ++j) {
            float4 v0 = xv[2*j], v1 = xv[2*j+1];
            int c = h * 64 + 8 * j;
            float2 p0 = lnp[c],   p1 = lnp[c+1], p2 = lnp[c+2], p3 = lnp[c+3];
            float2 p4 = lnp[c+4], p5 = lnp[c+5], p6 = lnp[c+6], p7 = lnp[c+7];
            uint4 o;
            o.x = pack_bf2((v0.x-mu)*rs*p0.x+p0.y, (v0.y-mu)*rs*p1.x+p1.y);
            o.y = pack_bf2((v0.z-mu)*rs*p2.x+p2.y, (v0.w-mu)*rs*p3.x+p3.y);
            o.z = pack_bf2((v1.x-mu)*rs*p4.x+p4.y, (v1.y-mu)*rs*p5.x+p5.y);
            o.w = pack_bf2((v1.z-mu)*rs*p6.x+p6.y, (v1.w-mu)*rs*p7.x+p7.y);
            *(uint4*)(rowb + j * 16) = o;
        }
        __syncwarp();

        const char* ar0 = sm + (m0 + r) * SA;
        uint32_t gsave[16];

        #pragma unroll 1
        for (int half = 0; half < 2; ++half) {
            float acc[16][4];
            #pragma unroll
            for (int nb = 0; nb < 16; ++nb)
                { acc[nb][0]=0.f; acc[nb][1]=0.f; acc[nb][2]=0.f; acc[nb][3]=0.f; }

            #pragma unroll 1
            for (int ks = 0; ks < 8; ++ks) {
                int kb = 32 * ks + 4 * q;
                uint32_t a0 = *(const uint32_t*)(ar0 + kb);
                uint32_t a1 = *(const uint32_t*)(ar0 + 8 * SA + kb);
                uint32_t a2 = *(const uint32_t*)(ar0 + kb + 16);
                uint32_t a3 = *(const uint32_t*)(ar0 + 8 * SA + kb + 16);
                const uint2* fb = (const uint2*)(sm + KA_FW1) + ks * 1024 + half * 512 + lane;
                #pragma unroll
                for (int nb = 0; nb < 16; ++nb) {
                    uint2 b = fb[nb * 32];
                    mma_bf16(acc[nb], a0, a1, a2, a3, b.x, b.y);
                }
            }

            #pragma unroll
            for (int nb = 0; nb < 16; ++nb) {
                int nbg = half * 16 + nb;
                int n0 = 8 * nbg + 2 * q, j = 4 * nbg + q;
                float2 e0 = ewp[n0], e1 = ewp[n0 + 1];
                float lo = (acc[nb][0]*e0.x + e0.y) * (acc[nb][1]*e1.x + e1.y);
                float hi = (acc[nb][2]*e0.x + e0.y) * (acc[nb][3]*e1.x + e1.y);
                float g = lo + hi;
                g += __shfl_xor_sync(0xffffffffu, g, 4);
                g += __shfl_xor_sync(0xffffffffu, g, 8);
                g += __shfl_xor_sync(0xffffffffu, g, 16);
                if (r == 0) gapw[warp * 128 + j] = g;
                if (half == 0) {
                    gsave[nb] = pack_bf2(lo, hi);
                } else {
                    *(__nv_bfloat16*)(sm + (m0 + r)     * SA + j * 2) = __float2bfloat16(lo);
                    *(__nv_bfloat16*)(sm + (m0 + r + 8) * SA + j * 2) = __float2bfloat16(hi);
                }
            }
            __syncwarp();
        }
        #pragma unroll
        for (int nb = 0; nb < 16; ++nb) {
            int j = 4 * nb + q;
            float2 v = unpack_bf2(gsave[nb]);
            *(__nv_bfloat16*)(sm + (m0 + r)     * SA + j * 2) = __float2bfloat16(v.x);
            *(__nv_bfloat16*)(sm + (m0 + r + 8) * SA + j * 2) = __float2bfloat16(v.y);
        }
        __syncwarp();

        // ---- coalesced copy to g_s ----
        #pragma unroll
        for (int i = 0; i < 8; ++i) {
            int u = lane + 32 * i, row = u >> 4, ch = u & 15;
            uint4 v = *(const uint4*)(sm + (m0 + row) * SA + ch * 16);
            ((uint4*)g_s)[((size_t)(tile * 128 + m0 + row)) * 16 + ch] = v;
        }

        // ---- GAP partial: sum 8 warps in fixed order ----
        __syncthreads();
        if (tid < 128) {
            float s = 0.f;
            #pragma unroll
            for (int w = 0; w < 8; ++w) s += gapw[w * 128 + tid];
            g_gpart[tile * 128 + tid] = s;
        }
        __syncthreads();
    }
}

// =====================================================================
// k2_se: merged GAP reduce (4-way over tiles) + SE matvec (4-way over k)
// grid = 8 (batch), 512 threads. Fully deterministic fixed-order sums.
// =====================================================================
__global__ void k2_se(const float* __restrict__ wse, const float* __restrict__ bse)
{
    __shared__ float red[4][128];
    __shared__ float gap[128];
    __shared__ float ps[4][128];
    const int b = blockIdx.x, tid = threadIdx.x;
    const int c = tid & 127, g = tid >> 7;

    float s = 0.f;
    const float* src = g_gpart + (size_t)(b * TPB + g * 72) * 128 + c;
    #pragma unroll 8
    for (int i = 0; i < 72; ++i) s += src[(size_t)i * 128];
    red[g][c] = s;
    __syncthreads();
    if (tid < 128)
        gap[tid] = ((red[0][tid] + red[1][tid]) + (red[2][tid] + red[3][tid])) * (1.f / PIXPB);
    __syncthreads();

    float a = 0.f;
    #pragma unroll 8
    for (int kk = 0; kk < 32; ++kk) {
        int k = 32 * g + kk;
        a += gap[k] * wse[k * 128 + c];
    }
    ps[g][c] = a;
    __syncthreads();
    if (tid < 128)
        g_att[b * 128 + tid] = bse[tid] +
            ((ps[0][tid] + ps[1][tid]) + (ps[2][tid] + ps[3][tid]));
}

// =====================================================================
// kB: 256 thr, 8 warps x 16 rows, batch-fixed CTAs (18 per batch).
//     att folded into w2 frags at init. cp.async cross-tile prefetch.
//     mma(w2·att) -> xm + LN2 -> mma(wf1, 2 x n128) -> gate -> mma(wf2) -> out
// =====================================================================
#define KB_XM    38912
#define KB_FWF1  (KB_XM + 67584)
#define KB_FW2   (KB_FWF1 + 65536)
#define KB_E2    (KB_FW2 + 32768)
#define KB_ELN   (KB_E2 + 1024)
#define KB_EBF1  (KB_ELN + 1024)
#define KB_EGAM  (KB_EBF1 + 1024)
#define KB_ATT   (KB_EGAM + 1024)
#define KB_SMEM  (KB_ATT + 512)

__global__ void __launch_bounds__(256, 1)
kB_ffn(const float* __restrict__ x,
       const float* __restrict__ b2,   const float* __restrict__ beta,
       const float* __restrict__ ln2s, const float* __restrict__ ln2b,
       const float* __restrict__ bf1,  const float* __restrict__ bf2,
       const float* __restrict__ gamma, float* __restrict__ out)
{
    extern __shared__ char sm[];
    const int tid = threadIdx.x, lane = tid & 31, warp = tid >> 5;
    const int q = lane & 3, r = lane >> 2, m0 = warp * 16;
    const uint32_t sm_base = smem_u32(sm);
    const int batch = blockIdx.x / 18, sub = blockIdx.x % 18;
    const int tbase = batch * TPB + sub;

    {
        uint4* d1 = (uint4*)(sm + KB_FWF1);
        const uint4* s1p = (const uint4*)g_fwf1;
        for (int i = tid; i < 4096; i += 256) d1[i] = s1p[i];
        uint4* d2 = (uint4*)(sm + KB_FW2);
        const uint4* s2p = (const uint4*)g_fw2;
        for (int i = tid; i < 2048; i += 256) d2[i] = s2p[i];
        if (tid < 128) {
            float be = beta[tid], ga = gamma[tid];
            ((float2*)(sm + KB_E2  ))[tid] = make_float2(be, be * b2[tid]);
            ((float2*)(sm + KB_ELN ))[tid] = make_float2(ln2s[tid], ln2b[tid]);
            ((float2*)(sm + KB_EGAM))[tid] = make_float2(ga, ga * bf2[tid]);
            ((float*)(sm + KB_ATT))[tid] = g_att[batch * 128 + tid];
        }
        if (tid < 256) {
            int n = tid, o = (n >> 1) + (n & 1) * 128;
            ((float*)(sm + KB_EBF1))[n] = bf1[o];
        }
    }
    __syncthreads();

    // ---- scale staged w2 frags by att (once per CTA) ----
    {
        const float* attv = (const float*)(sm + KB_ATT);
        uint2* p = (uint2*)(sm + KB_FW2);
        for (int i = tid; i < 4096; i += 256) {
            int lane2 = i & 31, ks = i >> 9;
            int k0 = 16 * ks + 2 * (lane2 & 3);
            uint2 v = p[i];
            float2 a0 = unpack_bf2(v.x), a1 = unpack_bf2(v.y);
            v.x = pack_bf2(a0.x * attv[k0],     a0.y * attv[k0 + 1]);
            v.y = pack_bf2(a1.x * attv[k0 + 8], a1.y * attv[k0 + 9]);
            p[i] = v;
        }
    }
    __syncthreads();

    const float2* e2p  = (const float2*)(sm + KB_E2);
    const float2* elnp = (const float2*)(sm + KB_ELN);
    const float*  ebfp = (const float*)(sm + KB_EBF1);
    const float2* egap = (const float2*)(sm + KB_EGAM);
    float* xms = (float*)(sm + KB_XM);
    const int pl = tid >> 1, h = tid & 1;

    auto prefetch_s = [&](int t) {
        const char* sg = (const char*)(g_s + ((size_t)(t * 128 + pl)) * 64) + h * 128;
        uint32_t dst = sm_base + (uint32_t)pl * SA + h * 128;
        #pragma unroll
        for (int j = 0; j < 8; ++j)
            CP_ASYNC16(dst + j * 16, sg + j * 16);
    };
    auto prefetch_x = [&](int t) {
        const float* xg = x + ((size_t)(t * 128 + m0)) * 128;
        #pragma unroll
        for (int i = 0; i < 16; ++i) {
            int gidx = i * 32 + lane;
            int row = gidx >> 5, c16 = gidx & 31;
            uint32_t dst = sm_base + KB_XM + (uint32_t)(m0 + row) * 528 + c16 * 16;
            CP_ASYNC16(dst, xg + (size_t)row * 128 + c16 * 4);
        }
    };

    // prologue: prefetch first tile
    prefetch_s(tbase); CP_COMMIT();
    prefetch_x(tbase); CP_COMMIT();

    #pragma unroll 1
    for (int it = 0; it < 16; ++it) {
        const int tile = tbase + 18 * it;
        const char* ar0 = sm + (m0 + r) * SA;

        // ---- s ready ----
        CP_WAIT1();
        __syncwarp();

        // ---- GEMM w2 (frags pre-scaled by att; A = s) ----
        float acc[16][4];
        #pragma unroll
        for (int nb = 0; nb < 16; ++nb)
            { acc[nb][0]=0.f; acc[nb][1]=0.f; acc[nb][2]=0.f; acc[nb][3]=0.f; }
        #pragma unroll 1
        for (int ks = 0; ks < 8; ++ks) {
            int kb = 32 * ks + 4 * q;
            uint32_t a0 = *(const uint32_t*)(ar0 + kb);
            uint32_t a1 = *(const uint32_t*)(ar0 + 8 * SA + kb);
            uint32_t a2 = *(const uint32_t*)(ar0 + kb + 16);
            uint32_t a3 = *(const uint32_t*)(ar0 + 8 * SA + kb + 16);
            const uint2* fb = (const uint2*)(sm + KB_FW2) + ks * 512 + lane;
            #pragma unroll
            for (int nb = 0; nb < 16; ++nb) {
                uint2 b = fb[nb * 32];
                mma_bf16(acc[nb], a0, a1, a2, a3, b.x, b.y);
            }
        }

        // ---- xm = x + beta*(d+b2); stash f32; LN2 stats via quad shfl ----
        CP_WAIT0();
        __syncwarp();
        float s1a = 0.f, s2a = 0.f, s1b = 0.f, s2b = 0.f;
        #pragma unroll
        for (int nb = 0; nb < 16; ++nb) {
            int n0 = 8 * nb + 2 * q;
            float2 e0 = e2p[n0], e1 = e2p[n0 + 1];
            float* pa = xms + (m0 + r)     * 132 + n0;
            float* pb = xms + (m0 + r + 8) * 132 + n0;
            float2 xa = *(float2*)pa;
            float2 xb = *(float2*)pb;
            float m00 = xa.x + acc[nb][0]*e0.x + e0.y;
            float m01 = xa.y + acc[nb][1]*e1.x + e1.y;
            float m10 = xb.x + acc[nb][2]*e0.x + e0.y;
            float m11 = xb.y + acc[nb][3]*e1.x + e1.y;
            *(float2*)pa = make_float2(m00, m01);
            *(float2*)pb = make_float2(m10, m11);
            s1a += m00 + m01; s2a += m00*m00 + m01*m01;
            s1b += m10 + m11; s2b += m10*m10 + m11*m11;
        }
        s1a += __shfl_xor_sync(0xffffffffu, s1a, 1); s1a += __shfl_xor_sync(0xffffffffu, s1a, 2);
        s2a += __shfl_xor_sync(0xffffffffu, s2a, 1); s2a += __shfl_xor_sync(0xffffffffu, s2a, 2);
        s1b += __shfl_xor_sync(0xffffffffu, s1b, 1); s1b += __shfl_xor_sync(0xffffffffu, s1b, 2);
        s2b += __shfl_xor_sync(0xffffffffu, s2b, 1); s2b += __shfl_xor_sync(0xffffffffu, s2b, 2);
        const float mua = s1a * (1.f/128.f);
        const float rsa = rsqrtf(fmaxf(s2a * (1.f/128.f) - mua*mua, 0.f) + EPS);
        const float mub = s1b * (1.f/128.f);
        const float rsb = rsqrtf(fmaxf(s2b * (1.f/128.f) - mub*mub, 0.f) + EPS);

        // ---- A2 = LN2(xm) -> atile bf16 ----
        #pragma unroll
        for (int nb = 0; nb < 16; ++nb) {
            int n0 = 8 * nb + 2 * q;
            float2 p0 = elnp[n0], p1 = elnp[n0 + 1];
            float2 va = *(const float2*)(xms + (m0 + r)     * 132 + n0);
            float2 vb = *(const float2*)(xms + (m0 + r + 8) * 132 + n0);
            *(uint32_t*)(sm + (m0 + r)     * SA + n0 * 2) =
                pack_bf2((va.x-mua)*rsa*p0.x+p0.y, (va.y-mua)*rsa*p1.x+p1.y);
            *(uint32_t*)(sm + (m0 + r + 8) * SA + n0 * 2) =
                pack_bf2((vb.x-mub)*rsb*p0.x+p0.y, (vb.y-mub)*rsb*p1.x+p1.y);
        }
        __syncwarp();

        // ---- GEMM wf1 (paired, 2 x n128 passes) ----
        uint32_t gsave[16];
        #pragma unroll 1
        for (int half = 0; half < 2; ++half) {
            float acc2[16][4];
            #pragma unroll
            for (int nb = 0; nb < 16; ++nb)
                { acc2[nb][0]=0.f; acc2[nb][1]=0.f; acc2[nb][2]=0.f; acc2[nb][3]=0.f; }
            #pragma unroll 1
            for (int ks = 0; ks < 8; ++ks) {
                int kb = 32 * ks + 4 * q;
                uint32_t a0 = *(const uint32_t*)(ar0 + kb);
                uint32_t a1 = *(const uint32_t*)(ar0 + 8 * SA + kb);
                uint32_t a2 = *(const uint32_t*)(ar0 + kb + 16);
                uint32_t a3 = *(const uint32_t*)(ar0 + 8 * SA + kb + 16);
                const uint2* fb = (const uint2*)(sm + KB_FWF1) + ks * 1024 + half * 512 + lane;
                #pragma unroll
                for (int nb = 0; nb < 16; ++nb) {
                    uint2 b = fb[nb * 32];
                    mma_bf16(acc2[nb], a0, a1, a2, a3, b.x, b.y);
                }
            }
            #pragma unroll
            for (int nb = 0; nb < 16; ++nb) {
                int nbg = half * 16 + nb;
                int n0 = 8 * nbg + 2 * q, j = 4 * nbg + q;
                float e0 = ebfp[n0], e1 = ebfp[n0 + 1];
                float lo = (acc2[nb][0] + e0) * (acc2[nb][1] + e1);
                float hi = (acc2[nb][2] + e0) * (acc2[nb][3] + e1);
                if (half == 0) {
                    gsave[nb] = pack_bf2(lo, hi);
                } else {
                    *(__nv_bfloat16*)(sm + (m0 + r)     * SA + j * 2) = __float2bfloat16(lo);
                    *(__nv_bfloat16*)(sm + (m0 + r + 8) * SA + j * 2) = __float2bfloat16(hi);
                }
            }
            __syncwarp();
        }
        #pragma unroll
        for (int nb = 0; nb < 16; ++nb) {
            int j = 4 * nb + q;
            float2 v = unpack_bf2(gsave[nb]);
            *(__nv_bfloat16*)(sm + (m0 + r)     * SA + j * 2) = __float2bfloat16(v.x);
            *(__nv_bfloat16*)(sm + (m0 + r + 8) * SA + j * 2) = __float2bfloat16(v.y);
        }
        __syncwarp();

        // ---- GEMM wf2 (n128), frags via LDG.64 ----
        float acc3[16][4];
        #pragma unroll
        for (int nb = 0; nb < 16; ++nb)
            { acc3[nb][0]=0.f; acc3[nb][1]=0.f; acc3[nb][2]=0.f; acc3[nb][3]=0.f; }
        #pragma unroll 1
        for (int ks = 0; ks < 8; ++ks) {
            int kb = 32 * ks + 4 * q;
            uint32_t a0 = *(const uint32_t*)(ar0 + kb);
            uint32_t a1 = *(const uint32_t*)(ar0 + 8 * SA + kb);
            uint32_t a2 = *(const uint32_t*)(ar0 + kb + 16);
            uint32_t a3 = *(const uint32_t*)(ar0 + 8 * SA + kb + 16);
            const uint2* fb = (const uint2*)g_fwf2 + ks * 512 + lane;
            #pragma unroll
            for (int nb = 0; nb < 16; ++nb) {
                uint2 b = __ldg(fb + nb * 32);
                mma_bf16(acc3[nb], a0, a1, a2, a3, b.x, b.y);
            }
        }

        // ---- prefetch next tile's s (atile is dead now) ----
        if (it < 15) { prefetch_s(tile + 18); CP_COMMIT(); }

        // ---- out = xm + gamma*(d+bf2) ----
        float* or0 = out + ((size_t)(tile * 128 + m0 + r)) * 128;
        float* or8 = or0 + (size_t)8 * 128;
        #pragma unroll
        for (int nb = 0; nb < 16; ++nb) {
            int n0 = 8 * nb + 2 * q;
            float2 g0 = egap[n0], g1 = egap[n0 + 1];
            float2 va = *(const float2*)(xms + (m0 + r)     * 132 + n0);
            float2 vb = *(const float2*)(xms + (m0 + r + 8) * 132 + n0);
            *(float2*)(or0 + n0) = make_float2(va.x + acc3[nb][0]*g0.x + g0.y,
                                               va.y + acc3[nb][1]*g1.x + g1.y);
            *(float2*)(or8 + n0) = make_float2(vb.x + acc3[nb][2]*g0.x + g0.y,
                                               vb.y + acc3[nb][3]*g1.x + g1.y);
        }

        // ---- prefetch next tile's x (xm region is dead now) ----
        if (it < 15) { prefetch_x(tile + 18); CP_COMMIT(); }
        __syncwarp();
    }
}

// =====================================================================
// launch
// =====================================================================
extern "C" void kernel_launch(void* const* d_in, const int* in_sizes, int n_in,
                              void* d_out, int out_size)
{
    (void)in_sizes; (void)n_in; (void)out_size;
    const float* x     = (const float*)d_in[0];
    const float* ln1s  = (const float*)d_in[1];
    const float* ln1b  = (const float*)d_in[2];
    const float* w1    = (const float*)d_in[3];
    const float* b1    = (const float*)d_in[4];
    const float* wdw   = (const float*)d_in[5];
    const float* bdw   = (const float*)d_in[6];
    const float* wse   = (const float*)d_in[7];
    const float* bse   = (const float*)d_in[8];
    const float* w2    = (const float*)d_in[9];
    const float* b2    = (const float*)d_in[10];
    const float* ln2s  = (const float*)d_in[11];
    const float* ln2b  = (const float*)d_in[12];
    const float* wf1   = (const float*)d_in[13];
    const float* bf1   = (const float*)d_in[14];
    const float* wf2   = (const float*)d_in[15];
    const float* bf2   = (const float*)d_in[16];
    const float* beta  = (const float*)d_in[17];
    const float* gamma = (const float*)d_in[18];
    float* out = (float*)d_out;

    cudaFuncSetAttribute(kA_spatial, cudaFuncAttributeMaxDynamicSharedMemorySize, KA_SMEM);
    cudaFuncSetAttribute(kB_ffn,     cudaFuncAttributeMaxDynamicSharedMemorySize, KB_SMEM);

    k0_frags<<<64, 256>>>(w1, w2, wf1, wf2);
    kA_spatial<<<GRID_A, 256, KA_SMEM>>>(x, ln1s, ln1b, b1, wdw, bdw);
    k2_se<<<B_, 512>>>(wse, bse);
    kB_ffn<<<GRID_B, 256, KB_SMEM>>>(x, b2, beta, ln2s, ln2b, bf1, bf2, gamma, out);
}

// round 11
// speedup vs baseline: 1.1328x; 1.0413x over previous
#include <cuda_runtime.h>
#include <cuda_bf16.h>
#include <cstdint>

#define B_     8
#define C_     128
#define PIXPB  36864
#define NPIX   294912
#define NT     2304             // 128-pixel tiles
#define TPB    288              // tiles per batch
#define EPS    1e-6f
#define GRID_A 296
#define GRID_B 144              // 18 CTAs per batch x 16 tiles
#define SA     304              // A-tile row stride bytes (conflict-free)

// ---------------- device globals (no allocation) ----------------
__device__ uint32_t g_s[(size_t)NPIX * 64];   // gated branch bf16x2 [pix][64]
__device__ float    g_gpart[NT * 128];        // per-tile GAP partials
__device__ float    g_att[B_ * C_];
// mma.sync B-fragment images, pair-packed: [ks][(half)][nbp][lane][e4]
// e4 = {nbEven.b0, nbEven.b1, nbOdd.b0, nbOdd.b1} -> one uint4 per lane feeds 2 mmas
__device__ uint32_t g_fw1 [8 * 2 * 8 * 32 * 4];  // w1  (pair-permuted), N=256
__device__ uint32_t g_fwf1[8 * 2 * 8 * 32 * 4];  // wf1 (pair-permuted), N=256
__device__ uint32_t g_fw2 [8 * 8 * 32 * 4];      // w2, N=128
__device__ uint32_t g_fwf2[8 * 8 * 32 * 4];      // wf2, N=128

__device__ __forceinline__ uint32_t pack_bf2(float a, float b) {
    __nv_bfloat162 h = __floats2bfloat162_rn(a, b);   // low = a
    return *reinterpret_cast<uint32_t*>(&h);
}
__device__ __forceinline__ float2 unpack_bf2(uint32_t w) {
    __nv_bfloat162 h = *reinterpret_cast<const __nv_bfloat162*>(&w);
    return make_float2(__low2float(h), __high2float(h));
}
__device__ __forceinline__ void mma_bf16(float* c, uint32_t a0, uint32_t a1,
                                         uint32_t a2, uint32_t a3,
                                         uint32_t b0, uint32_t b1) {
    asm volatile(
        "mma.sync.aligned.m16n8k16.row.col.f32.bf16.bf16.f32 "
        "{%0,%1,%2,%3}, {%4,%5,%6,%7}, {%8,%9}, {%0,%1,%2,%3};\n"
        : "+f"(c[0]), "+f"(c[1]), "+f"(c[2]), "+f"(c[3])
        : "r"(a0), "r"(a1), "r"(a2), "r"(a3), "r"(b0), "r"(b1));
}
__device__ __forceinline__ uint32_t smem_u32(const void* p) {
    uint32_t a;
    asm("{ .reg .u64 t; cvta.to.shared.u64 t, %1; cvt.u32.u64 %0, t; }" : "=r"(a) : "l"(p));
    return a;
}
#define CP_ASYNC16(dst, src) \
    asm volatile("cp.async.ca.shared.global [%0], [%1], 16;" :: "r"(dst), "l"(src))
#define CP_COMMIT()  asm volatile("cp.async.commit_group;" ::: "memory")
#define CP_WAIT1()   asm volatile("cp.async.wait_group 1;" ::: "memory")
#define CP_WAIT0()   asm volatile("cp.async.wait_group 0;" ::: "memory")

// =====================================================================
// k0: pair-packed B-fragment images.
// m16n8k16 col-B frag: lane holds B[k][n], n = 8nb + lane/4,
// k = 16ks + 2*(lane%4) + 8e. w1/wf1 pair-permuted: n -> (n>>1)+(n&1)*128
// =====================================================================
__global__ void k0_frags(const float* __restrict__ w1, const float* __restrict__ w2,
                         const float* __restrict__ wf1, const float* __restrict__ wf2)
{
    int i0 = blockIdx.x * blockDim.x + threadIdx.x, str = gridDim.x * blockDim.x;
    // n256 images: [ks][half][nbp][lane][e4] = 16384 words
    for (int i = i0; i < 16384; i += str) {
        int e4 = i & 3, lane = (i >> 2) & 31, nbp = (i >> 7) & 7;
        int half = (i >> 10) & 1, ks = i >> 11;
        int nbg = half * 16 + 2 * nbp + (e4 >> 1);
        int e = e4 & 1;
        int n = 8 * nbg + (lane >> 2);
        int k = 16 * ks + 2 * (lane & 3) + 8 * e;
        int o = (n >> 1) + (n & 1) * 128;
        g_fw1 [i] = pack_bf2(w1 [k * 256 + o], w1 [(k + 1) * 256 + o]);
        g_fwf1[i] = pack_bf2(wf1[k * 256 + o], wf1[(k + 1) * 256 + o]);
    }
    // n128 images: [ks][nbp][lane][e4] = 8192 words
    for (int i = i0; i < 8192; i += str) {
        int e4 = i & 3, lane = (i >> 2) & 31, nbp = (i >> 7) & 7, ks = i >> 10;
        int nb = 2 * nbp + (e4 >> 1);
        int e = e4 & 1;
        int n = 8 * nb + (lane >> 2);
        int k = 16 * ks + 2 * (lane & 3) + 8 * e;
        g_fw2 [i] = pack_bf2(w2 [k * 128 + n], w2 [(k + 1) * 128 + n]);
        g_fwf2[i] = pack_bf2(wf2[k * 128 + n], wf2[(k + 1) * 128 + n]);
    }
}

// =====================================================================
// kA: 256 thr, 8 warps x 16 rows, 2 CTAs/SM. LN1 -> mma(w1, 2 x n128)
//     -> dw-affine + gate -> g_s + per-tile GAP.
// =====================================================================
#define KA_FW1  38912
#define KA_EW   (KA_FW1 + 65536)
#define KA_LN   (KA_EW + 2048)
#define KA_GAP  (KA_LN + 1024)
#define KA_SMEM (KA_GAP + 4096)   // 111616

__global__ void __launch_bounds__(256, 2)
kA_spatial(const float* __restrict__ x,
           const float* __restrict__ ln1s, const float* __restrict__ ln1b,
           const float* __restrict__ b1,   const float* __restrict__ wdw,
           const float* __restrict__ bdw)
{
    extern __shared__ char sm[];
    const int tid = threadIdx.x, lane = tid & 31, warp = tid >> 5;
    const int q = lane & 3, r = lane >> 2, m0 = warp * 16;

    {
        uint4* dst = (uint4*)(sm + KA_FW1);
        const uint4* src = (const uint4*)g_fw1;
        for (int i = tid; i < 4096; i += 256) dst[i] = src[i];
        if (tid < 256) {
            int n = tid, o = (n >> 1) + (n & 1) * 128;
            float w = wdw[o];
            ((float2*)(sm + KA_EW))[n] = make_float2(w, b1[o] * w + bdw[o]);
        }
        if (tid < 128)
            ((float2*)(sm + KA_LN))[tid] = make_float2(ln1s[tid], ln1b[tid]);
    }
    __syncthreads();

    const float2* ewp = (const float2*)(sm + KA_EW);
    const float2* lnp = (const float2*)(sm + KA_LN);
    float* gapw = (float*)(sm + KA_GAP);
    const int pl = tid >> 1, h = tid & 1;

    for (int tile = blockIdx.x; tile < NT; tile += GRID_A) {
        // ---- LN1: thread = (pixel pl, channel half h) ----
        const float4* xr = (const float4*)x + ((size_t)(tile * 128 + pl)) * 32 + h * 16;
        float4 xv[16];
        float s1 = 0.f, s2 = 0.f;
        #pragma unroll
        for (int i = 0; i < 16; ++i) {
            xv[i] = xr[i];
            s1 += xv[i].x + xv[i].y + xv[i].z + xv[i].w;
            s2 += xv[i].x*xv[i].x + xv[i].y*xv[i].y + xv[i].z*xv[i].z + xv[i].w*xv[i].w;
        }
        s1 += __shfl_xor_sync(0xffffffffu, s1, 1);
        s2 += __shfl_xor_sync(0xffffffffu, s2, 1);
        const float mu = s1 * (1.f/128.f);
        const float rs = rsqrtf(fmaxf(s2 * (1.f/128.f) - mu*mu, 0.f) + EPS);

        char* rowb = sm + pl * SA + h * 128;
        #pragma unroll
        for (int j = 0; j < 8; ++j) {
            float4 v0 = xv[2*j], v1 = xv[2*j+1];
            int c = h * 64 + 8 * j;
            float2 p0 = lnp[c],   p1 = lnp[c+1], p2 = lnp[c+2], p3 = lnp[c+3];
            float2 p4 = lnp[c+4], p5 = lnp[c+5], p6 = lnp[c+6], p7 = lnp[c+7];
            uint4 o;
            o.x = pack_bf2((v0.x-mu)*rs*p0.x+p0.y, (v0.y-mu)*rs*p1.x+p1.y);
            o.y = pack_bf2((v0.z-mu)*rs*p2.x+p2.y, (v0.w-mu)*rs*p3.x+p3.y);
            o.z = pack_bf2((v1.x-mu)*rs*p4.x+p4.y, (v1.y-mu)*rs*p5.x+p5.y);
            o.w = pack_bf2((v1.z-mu)*rs*p6.x+p6.y, (v1.w-mu)*rs*p7.x+p7.y);
            *(uint4*)(rowb + j * 16) = o;
        }
        __syncwarp();

        const char* ar0 = sm + (m0 + r) * SA;
        uint32_t gsave[16];

        #pragma unroll 1
        for (int half = 0; half < 2; ++half) {
            float acc[16][4];
            #pragma unroll
            for (int nb = 0; nb < 16; ++nb)
                { acc[nb][0]=0.f; acc[nb][1]=0.f; acc[nb][2]=0.f; acc[nb][3]=0.f; }

            #pragma unroll 1
            for (int ks = 0; ks < 8; ++ks) {
                int kb = 32 * ks + 4 * q;
                uint32_t a0 = *(const uint32_t*)(ar0 + kb);
                uint32_t a1 = *(const uint32_t*)(ar0 + 8 * SA + kb);
                uint32_t a2 = *(const uint32_t*)(ar0 + kb + 16);
                uint32_t a3 = *(const uint32_t*)(ar0 + 8 * SA + kb + 16);
                const uint4* fb = (const uint4*)(sm + KA_FW1) + (ks * 2 + half) * 256 + lane;
                #pragma unroll
                for (int nbp = 0; nbp < 8; ++nbp) {
                    uint4 b = fb[nbp * 32];
                    mma_bf16(acc[2*nbp],   a0, a1, a2, a3, b.x, b.y);
                    mma_bf16(acc[2*nbp+1], a0, a1, a2, a3, b.z, b.w);
                }
            }

            #pragma unroll
            for (int nb = 0; nb < 16; ++nb) {
                int nbg = half * 16 + nb;
                int n0 = 8 * nbg + 2 * q, j = 4 * nbg + q;
                float2 e0 = ewp[n0], e1 = ewp[n0 + 1];
                float lo = (acc[nb][0]*e0.x + e0.y) * (acc[nb][1]*e1.x + e1.y);
                float hi = (acc[nb][2]*e0.x + e0.y) * (acc[nb][3]*e1.x + e1.y);
                float g = lo + hi;
                g += __shfl_xor_sync(0xffffffffu, g, 4);
                g += __shfl_xor_sync(0xffffffffu, g, 8);
                g += __shfl_xor_sync(0xffffffffu, g, 16);
                if (r == 0) gapw[warp * 128 + j] = g;
                if (half == 0) {
                    gsave[nb] = pack_bf2(lo, hi);
                } else {
                    *(__nv_bfloat16*)(sm + (m0 + r)     * SA + j * 2) = __float2bfloat16(lo);
                    *(__nv_bfloat16*)(sm + (m0 + r + 8) * SA + j * 2) = __float2bfloat16(hi);
                }
            }
            __syncwarp();
        }
        #pragma unroll
        for (int nb = 0; nb < 16; ++nb) {
            int j = 4 * nb + q;
            float2 v = unpack_bf2(gsave[nb]);
            *(__nv_bfloat16*)(sm + (m0 + r)     * SA + j * 2) = __float2bfloat16(v.x);
            *(__nv_bfloat16*)(sm + (m0 + r + 8) * SA + j * 2) = __float2bfloat16(v.y);
        }
        __syncwarp();

        // ---- coalesced copy to g_s ----
        #pragma unroll
        for (int i = 0; i < 8; ++i) {
            int u = lane + 32 * i, row = u >> 4, ch = u & 15;
            uint4 v = *(const uint4*)(sm + (m0 + row) * SA + ch * 16);
            ((uint4*)g_s)[((size_t)(tile * 128 + m0 + row)) * 16 + ch] = v;
        }

        // ---- GAP partial: sum 8 warps in fixed order ----
        __syncthreads();
        if (tid < 128) {
            float s = 0.f;
            #pragma unroll
            for (int w = 0; w < 8; ++w) s += gapw[w * 128 + tid];
            g_gpart[tile * 128 + tid] = s;
        }
        __syncthreads();
    }
}

// =====================================================================
// k2_se: merged GAP reduce (4-way over tiles) + SE matvec (4-way over k)
// =====================================================================
__global__ void k2_se(const float* __restrict__ wse, const float* __restrict__ bse)
{
    __shared__ float red[4][128];
    __shared__ float gap[128];
    __shared__ float ps[4][128];
    const int b = blockIdx.x, tid = threadIdx.x;
    const int c = tid & 127, g = tid >> 7;

    float s = 0.f;
    const float* src = g_gpart + (size_t)(b * TPB + g * 72) * 128 + c;
    #pragma unroll 8
    for (int i = 0; i < 72; ++i) s += src[(size_t)i * 128];
    red[g][c] = s;
    __syncthreads();
    if (tid < 128)
        gap[tid] = ((red[0][tid] + red[1][tid]) + (red[2][tid] + red[3][tid])) * (1.f / PIXPB);
    __syncthreads();

    float a = 0.f;
    #pragma unroll 8
    for (int kk = 0; kk < 32; ++kk) {
        int k = 32 * g + kk;
        a += gap[k] * wse[k * 128 + c];
    }
    ps[g][c] = a;
    __syncthreads();
    if (tid < 128)
        g_att[b * 128 + tid] = bse[tid] +
            ((ps[0][tid] + ps[1][tid]) + (ps[2][tid] + ps[3][tid]));
}

// =====================================================================
// kB: 256 thr, 8 warps x 16 rows, batch-fixed CTAs (18 per batch).
//     att folded into w2 frags. cp.async cross-tile prefetch. ks unroll 2.
// =====================================================================
#define KB_XM    38912
#define KB_FWF1  (KB_XM + 67584)
#define KB_FW2   (KB_FWF1 + 65536)
#define KB_E2    (KB_FW2 + 32768)
#define KB_ELN   (KB_E2 + 1024)
#define KB_EBF1  (KB_ELN + 1024)
#define KB_EGAM  (KB_EBF1 + 1024)
#define KB_ATT   (KB_EGAM + 1024)
#define KB_SMEM  (KB_ATT + 512)

__global__ void __launch_bounds__(256, 1)
kB_ffn(const float* __restrict__ x,
       const float* __restrict__ b2,   const float* __restrict__ beta,
       const float* __restrict__ ln2s, const float* __restrict__ ln2b,
       const float* __restrict__ bf1,  const float* __restrict__ bf2,
       const float* __restrict__ gamma, float* __restrict__ out)
{
    extern __shared__ char sm[];
    const int tid = threadIdx.x, lane = tid & 31, warp = tid >> 5;
    const int q = lane & 3, r = lane >> 2, m0 = warp * 16;
    const uint32_t sm_base = smem_u32(sm);
    const int batch = blockIdx.x / 18, sub = blockIdx.x % 18;
    const int tbase = batch * TPB + sub;

    {
        uint4* d1 = (uint4*)(sm + KB_FWF1);
        const uint4* s1p = (const uint4*)g_fwf1;
        for (int i = tid; i < 4096; i += 256) d1[i] = s1p[i];
        uint4* d2 = (uint4*)(sm + KB_FW2);
        const uint4* s2p = (const uint4*)g_fw2;
        for (int i = tid; i < 2048; i += 256) d2[i] = s2p[i];
        if (tid < 128) {
            float be = beta[tid], ga = gamma[tid];
            ((float2*)(sm + KB_E2  ))[tid] = make_float2(be, be * b2[tid]);
            ((float2*)(sm + KB_ELN ))[tid] = make_float2(ln2s[tid], ln2b[tid]);
            ((float2*)(sm + KB_EGAM))[tid] = make_float2(ga, ga * bf2[tid]);
            ((float*)(sm + KB_ATT))[tid] = g_att[batch * 128 + tid];
        }
        if (tid < 256) {
            int n = tid, o = (n >> 1) + (n & 1) * 128;
            ((float*)(sm + KB_EBF1))[n] = bf1[o];
        }
    }
    __syncthreads();

    // ---- scale staged w2 frags by att (once per CTA; pair-packed layout) ----
    {
        const float* attv = (const float*)(sm + KB_ATT);
        uint4* p = (uint4*)(sm + KB_FW2);
        for (int i = tid; i < 2048; i += 256) {
            int lane2 = i & 31, ks = i >> 8;        // i = (ks*8+nbp)*32 + lane
            int k0 = 16 * ks + 2 * (lane2 & 3);
            uint4 v = p[i];
            float2 w0 = unpack_bf2(v.x), w1v = unpack_bf2(v.y);
            float2 w2v = unpack_bf2(v.z), w3v = unpack_bf2(v.w);
            v.x = pack_bf2(w0.x  * attv[k0],     w0.y  * attv[k0 + 1]);
            v.y = pack_bf2(w1v.x * attv[k0 + 8], w1v.y * attv[k0 + 9]);
            v.z = pack_bf2(w2v.x * attv[k0],     w2v.y * attv[k0 + 1]);
            v.w = pack_bf2(w3v.x * attv[k0 + 8], w3v.y * attv[k0 + 9]);
            p[i] = v;
        }
    }
    __syncthreads();

    const float2* e2p  = (const float2*)(sm + KB_E2);
    const float2* elnp = (const float2*)(sm + KB_ELN);
    const float*  ebfp = (const float*)(sm + KB_EBF1);
    const float2* egap = (const float2*)(sm + KB_EGAM);
    float* xms = (float*)(sm + KB_XM);
    const int pl = tid >> 1, h = tid & 1;

    auto prefetch_s = [&](int t) {
        const char* sg = (const char*)(g_s + ((size_t)(t * 128 + pl)) * 64) + h * 128;
        uint32_t dst = sm_base + (uint32_t)pl * SA + h * 128;
        #pragma unroll
        for (int j = 0; j < 8; ++j)
            CP_ASYNC16(dst + j * 16, sg + j * 16);
    };
    auto prefetch_x = [&](int t) {
        const float* xg = x + ((size_t)(t * 128 + m0)) * 128;
        #pragma unroll
        for (int i = 0; i < 16; ++i) {
            int gidx = i * 32 + lane;
            int row = gidx >> 5, c16 = gidx & 31;
            uint32_t dst = sm_base + KB_XM + (uint32_t)(m0 + row) * 528 + c16 * 16;
            CP_ASYNC16(dst, xg + (size_t)row * 128 + c16 * 4);
        }
    };

    prefetch_s(tbase); CP_COMMIT();
    prefetch_x(tbase); CP_COMMIT();

    #pragma unroll 1
    for (int it = 0; it < 16; ++it) {
        const int tile = tbase + 18 * it;
        const char* ar0 = sm + (m0 + r) * SA;

        CP_WAIT1();
        __syncwarp();

        // ---- GEMM w2 (frags pre-scaled by att; A = s) ----
        float acc[16][4];
        #pragma unroll
        for (int nb = 0; nb < 16; ++nb)
            { acc[nb][0]=0.f; acc[nb][1]=0.f; acc[nb][2]=0.f; acc[nb][3]=0.f; }
        #pragma unroll 2
        for (int ks = 0; ks < 8; ++ks) {
            int kb = 32 * ks + 4 * q;
            uint32_t a0 = *(const uint32_t*)(ar0 + kb);
            uint32_t a1 = *(const uint32_t*)(ar0 + 8 * SA + kb);
            uint32_t a2 = *(const uint32_t*)(ar0 + kb + 16);
            uint32_t a3 = *(const uint32_t*)(ar0 + 8 * SA + kb + 16);
            const uint4* fb = (const uint4*)(sm + KB_FW2) + ks * 256 + lane;
            #pragma unroll
            for (int nbp = 0; nbp < 8; ++nbp) {
                uint4 b = fb[nbp * 32];
                mma_bf16(acc[2*nbp],   a0, a1, a2, a3, b.x, b.y);
                mma_bf16(acc[2*nbp+1], a0, a1, a2, a3, b.z, b.w);
            }
        }

        // ---- xm = x + beta*(d+b2); stash f32; LN2 stats via quad shfl ----
        CP_WAIT0();
        __syncwarp();
        float s1a = 0.f, s2a = 0.f, s1b = 0.f, s2b = 0.f;
        #pragma unroll
        for (int nb = 0; nb < 16; ++nb) {
            int n0 = 8 * nb + 2 * q;
            float2 e0 = e2p[n0], e1 = e2p[n0 + 1];
            float* pa = xms + (m0 + r)     * 132 + n0;
            float* pb = xms + (m0 + r + 8) * 132 + n0;
            float2 xa = *(float2*)pa;
            float2 xb = *(float2*)pb;
            float m00 = xa.x + acc[nb][0]*e0.x + e0.y;
            float m01 = xa.y + acc[nb][1]*e1.x + e1.y;
            float m10 = xb.x + acc[nb][2]*e0.x + e0.y;
            float m11 = xb.y + acc[nb][3]*e1.x + e1.y;
            *(float2*)pa = make_float2(m00, m01);
            *(float2*)pb = make_float2(m10, m11);
            s1a += m00 + m01; s2a += m00*m00 + m01*m01;
            s1b += m10 + m11; s2b += m10*m10 + m11*m11;
        }
        s1a += __shfl_xor_sync(0xffffffffu, s1a, 1); s1a += __shfl_xor_sync(0xffffffffu, s1a, 2);
        s2a += __shfl_xor_sync(0xffffffffu, s2a, 1); s2a += __shfl_xor_sync(0xffffffffu, s2a, 2);
        s1b += __shfl_xor_sync(0xffffffffu, s1b, 1); s1b += __shfl_xor_sync(0xffffffffu, s1b, 2);
        s2b += __shfl_xor_sync(0xffffffffu, s2b, 1); s2b += __shfl_xor_sync(0xffffffffu, s2b, 2);
        const float mua = s1a * (1.f/128.f);
        const float rsa = rsqrtf(fmaxf(s2a * (1.f/128.f) - mua*mua, 0.f) + EPS);
        const float mub = s1b * (1.f/128.f);
        const float rsb = rsqrtf(fmaxf(s2b * (1.f/128.f) - mub*mub, 0.f) + EPS);

        // ---- A2 = LN2(xm) -> atile bf16 ----
        #pragma unroll
        for (int nb = 0; nb < 16; ++nb) {
            int n0 = 8 * nb + 2 * q;
            float2 p0 = elnp[n0], p1 = elnp[n0 + 1];
            float2 va = *(const float2*)(xms + (m0 + r)     * 132 + n0);
            float2 vb = *(const float2*)(xms + (m0 + r + 8) * 132 + n0);
            *(uint32_t*)(sm + (m0 + r)     * SA + n0 * 2) =
                pack_bf2((va.x-mua)*rsa*p0.x+p0.y, (va.y-mua)*rsa*p1.x+p1.y);
            *(uint32_t*)(sm + (m0 + r + 8) * SA + n0 * 2) =
                pack_bf2((vb.x-mub)*rsb*p0.x+p0.y, (vb.y-mub)*rsb*p1.x+p1.y);
        }
        __syncwarp();

        // ---- GEMM wf1 (paired, 2 x n128 passes) ----
        uint32_t gsave[16];
        #pragma unroll 1
        for (int half = 0; half < 2; ++half) {
            float acc2[16][4];
            #pragma unroll
            for (int nb = 0; nb < 16; ++nb)
                { acc2[nb][0]=0.f; acc2[nb][1]=0.f; acc2[nb][2]=0.f; acc2[nb][3]=0.f; }
            #pragma unroll 2
            for (int ks = 0; ks < 8; ++ks) {
                int kb = 32 * ks + 4 * q;
                uint32_t a0 = *(const uint32_t*)(ar0 + kb);
                uint32_t a1 = *(const uint32_t*)(ar0 + 8 * SA + kb);
                uint32_t a2 = *(const uint32_t*)(ar0 + kb + 16);
                uint32_t a3 = *(const uint32_t*)(ar0 + 8 * SA + kb + 16);
                const uint4* fb = (const uint4*)(sm + KB_FWF1) + (ks * 2 + half) * 256 + lane;
                #pragma unroll
                for (int nbp = 0; nbp < 8; ++nbp) {
                    uint4 b = fb[nbp * 32];
                    mma_bf16(acc2[2*nbp],   a0, a1, a2, a3, b.x, b.y);
                    mma_bf16(acc2[2*nbp+1], a0, a1, a2, a3, b.z, b.w);
                }
            }
            #pragma unroll
            for (int nb = 0; nb < 16; ++nb) {
                int nbg = half * 16 + nb;
                int n0 = 8 * nbg + 2 * q, j = 4 * nbg + q;
                float e0 = ebfp[n0], e1 = ebfp[n0 + 1];
                float lo = (acc2[nb][0] + e0) * (acc2[nb][1] + e1);
                float hi = (acc2[nb][2] + e0) * (acc2[nb][3] + e1);
                if (half == 0) {
                    gsave[nb] = pack_bf2(lo, hi);
                } else {
                    *(__nv_bfloat16*)(sm + (m0 + r)     * SA + j * 2) = __float2bfloat16(lo);
                    *(__nv_bfloat16*)(sm + (m0 + r + 8) * SA + j * 2) = __float2bfloat16(hi);
                }
            }
            __syncwarp();
        }
        #pragma unroll
        for (int nb = 0; nb < 16; ++nb) {
            int j = 4 * nb + q;
            float2 v = unpack_bf2(gsave[nb]);
            *(__nv_bfloat16*)(sm + (m0 + r)     * SA + j * 2) = __float2bfloat16(v.x);
            *(__nv_bfloat16*)(sm + (m0 + r + 8) * SA + j * 2) = __float2bfloat16(v.y);
        }
        __syncwarp();

        // ---- GEMM wf2 (n128), frags via LDG.128 ----
        float acc3[16][4];
        #pragma unroll
        for (int nb = 0; nb < 16; ++nb)
            { acc3[nb][0]=0.f; acc3[nb][1]=0.f; acc3[nb][2]=0.f; acc3[nb][3]=0.f; }
        #pragma unroll 2
        for (int ks = 0; ks < 8; ++ks) {
            int kb = 32 * ks + 4 * q;
            uint32_t a0 = *(const uint32_t*)(ar0 + kb);
            uint32_t a1 = *(const uint32_t*)(ar0 + 8 * SA + kb);
            uint32_t a2 = *(const uint32_t*)(ar0 + kb + 16);
            uint32_t a3 = *(const uint32_t*)(ar0 + 8 * SA + kb + 16);
            const uint4* fb = (const uint4*)g_fwf2 + ks * 256 + lane;
            #pragma unroll
            for (int nbp = 0; nbp < 8; ++nbp) {
                uint4 b = __ldg(fb + nbp * 32);
                mma_bf16(acc3[2*nbp],   a0, a1, a2, a3, b.x, b.y);
                mma_bf16(acc3[2*nbp+1], a0, a1, a2, a3, b.z, b.w);
            }
        }

        // ---- prefetch next tile's s (atile is dead now) ----
        if (it < 15) { prefetch_s(tile + 18); CP_COMMIT(); }

        // ---- out = xm + gamma*(d+bf2) ----
        float* or0 = out + ((size_t)(tile * 128 + m0 + r)) * 128;
        float* or8 = or0 + (size_t)8 * 128;
        #pragma unroll
        for (int nb = 0; nb < 16; ++nb) {
            int n0 = 8 * nb + 2 * q;
            float2 g0 = egap[n0], g1 = egap[n0 + 1];
            float2 va = *(const float2*)(xms + (m0 + r)     * 132 + n0);
            float2 vb = *(const float2*)(xms + (m0 + r + 8) * 132 + n0);
            *(float2*)(or0 + n0) = make_float2(va.x + acc3[nb][0]*g0.x + g0.y,
                                               va.y + acc3[nb][1]*g1.x + g1.y);
            *(float2*)(or8 + n0) = make_float2(vb.x + acc3[nb][2]*g0.x + g0.y,
                                               vb.y + acc3[nb][3]*g1.x + g1.y);
        }

        // ---- prefetch next tile's x (xm region is dead now) ----
        if (it < 15) { prefetch_x(tile + 18); CP_COMMIT(); }
        __syncwarp();
    }
}

// =====================================================================
// launch
// =====================================================================
extern "C" void kernel_launch(void* const* d_in, const int* in_sizes, int n_in,
                              void* d_out, int out_size)
{
    (void)in_sizes; (void)n_in; (void)out_size;
    const float* x     = (const float*)d_in[0];
    const float* ln1s  = (const float*)d_in[1];
    const float* ln1b  = (const float*)d_in[2];
    const float* w1    = (const float*)d_in[3];
    const float* b1    = (const float*)d_in[4];
    const float* wdw   = (const float*)d_in[5];
    const float* bdw   = (const float*)d_in[6];
    const float* wse   = (const float*)d_in[7];
    const float* bse   = (const float*)d_in[8];
    const float* w2    = (const float*)d_in[9];
    const float* b2    = (const float*)d_in[10];
    const float* ln2s  = (const float*)d_in[11];
    const float* ln2b  = (const float*)d_in[12];
    const float* wf1   = (const float*)d_in[13];
    const float* bf1   = (const float*)d_in[14];
    const float* wf2   = (const float*)d_in[15];
    const float* bf2   = (const float*)d_in[16];
    const float* beta  = (const float*)d_in[17];
    const float* gamma = (const float*)d_in[18];
    float* out = (float*)d_out;

    cudaFuncSetAttribute(kA_spatial, cudaFuncAttributeMaxDynamicSharedMemorySize, KA_SMEM);
    cudaFuncSetAttribute(kB_ffn,     cudaFuncAttributeMaxDynamicSharedMemorySize, KB_SMEM);

    k0_frags<<<64, 256>>>(w1, w2, wf1, wf2);
    kA_spatial<<<GRID_A, 256, KA_SMEM>>>(x, ln1s, ln1b, b1, wdw, bdw);
    k2_se<<<B_, 512>>>(wse, bse);
    kB_ffn<<<GRID_B, 256, KB_SMEM>>>(x, b2, beta, ln2s, ln2b, bf1, bf2, gamma, out);
}

// round 12
// speedup vs baseline: 1.1748x; 1.0371x over previous
#include <cuda_runtime.h>
#include <cuda_bf16.h>
#include <cuda_fp8.h>
#include <cstdint>

#define B_     8
#define C_     128
#define PIXPB  36864
#define NPIX   294912
#define NT     2304             // 128-pixel tiles
#define TPB    288              // tiles per batch
#define EPS    1e-6f
#define GRID_A 296
#define GRID_B 144              // 18 CTAs per batch x 16 tiles
#define SA     304              // bf16 A-tile row stride bytes (conflict-free)
#define SA8    144              // fp8 A-tile row stride bytes (conflict-free)
#define W1SCL  8.0f             // w1 pre-scale into e4m3 normal range

// ---------------- device globals (no allocation) ----------------
__device__ uint32_t g_s[(size_t)NPIX * 64];   // gated branch bf16x2 [pix][64]
__device__ float    g_gpart[NT * 128];        // per-tile GAP partials
__device__ float    g_att[B_ * C_];
// w1 fp8 frag image (pair-permuted, x8 scaled): [ks4][half][nbp8][lane][e4] u32 (4x e4m3)
__device__ uint32_t g_fw1 [4 * 2 * 8 * 32 * 4];
// bf16 pair-packed images: [ks8][(half)][nbp][lane][e4] u32 (bf16x2)
__device__ uint32_t g_fwf1[8 * 2 * 8 * 32 * 4];  // wf1 (pair-permuted), N=256
__device__ uint32_t g_fw2 [8 * 8 * 32 * 4];      // w2, N=128
__device__ uint32_t g_fwf2[8 * 8 * 32 * 4];      // wf2, N=128

__device__ __forceinline__ uint32_t pack_bf2(float a, float b) {
    __nv_bfloat162 h = __floats2bfloat162_rn(a, b);   // low = a
    return *reinterpret_cast<uint32_t*>(&h);
}
__device__ __forceinline__ float2 unpack_bf2(uint32_t w) {
    __nv_bfloat162 h = *reinterpret_cast<const __nv_bfloat162*>(&w);
    return make_float2(__low2float(h), __high2float(h));
}
__device__ __forceinline__ uint32_t pack_e4m3x4(float f0, float f1, float f2, float f3) {
    uint16_t lo, hi;
    asm("cvt.rn.satfinite.e4m3x2.f32 %0, %1, %2;" : "=h"(lo) : "f"(f1), "f"(f0));
    asm("cvt.rn.satfinite.e4m3x2.f32 %0, %1, %2;" : "=h"(hi) : "f"(f3), "f"(f2));
    uint32_t r; asm("mov.b32 %0, {%1, %2};" : "=r"(r) : "h"(lo), "h"(hi));
    return r;
}
__device__ __forceinline__ void mma_bf16(float* c, uint32_t a0, uint32_t a1,
                                         uint32_t a2, uint32_t a3,
                                         uint32_t b0, uint32_t b1) {
    asm volatile(
        "mma.sync.aligned.m16n8k16.row.col.f32.bf16.bf16.f32 "
        "{%0,%1,%2,%3}, {%4,%5,%6,%7}, {%8,%9}, {%0,%1,%2,%3};\n"
        : "+f"(c[0]), "+f"(c[1]), "+f"(c[2]), "+f"(c[3])
        : "r"(a0), "r"(a1), "r"(a2), "r"(a3), "r"(b0), "r"(b1));
}
__device__ __forceinline__ void mma_fp8(float* c, uint32_t a0, uint32_t a1,
                                        uint32_t a2, uint32_t a3,
                                        uint32_t b0, uint32_t b1) {
    asm volatile(
        "mma.sync.aligned.m16n8k32.row.col.f32.e4m3.e4m3.f32 "
        "{%0,%1,%2,%3}, {%4,%5,%6,%7}, {%8,%9}, {%0,%1,%2,%3};\n"
        : "+f"(c[0]), "+f"(c[1]), "+f"(c[2]), "+f"(c[3])
        : "r"(a0), "r"(a1), "r"(a2), "r"(a3), "r"(b0), "r"(b1));
}
__device__ __forceinline__ uint32_t smem_u32(const void* p) {
    uint32_t a;
    asm("{ .reg .u64 t; cvta.to.shared.u64 t, %1; cvt.u32.u64 %0, t; }" : "=r"(a) : "l"(p));
    return a;
}
#define CP_ASYNC16(dst, src) \
    asm volatile("cp.async.ca.shared.global [%0], [%1], 16;" :: "r"(dst), "l"(src))
#define CP_COMMIT()  asm volatile("cp.async.commit_group;" ::: "memory")
#define CP_WAIT1()   asm volatile("cp.async.wait_group 1;" ::: "memory")
#define CP_WAIT0()   asm volatile("cp.async.wait_group 0;" ::: "memory")

// =====================================================================
// k0: fragment images.
// fp8 m16n8k32 col-B frag: lane holds B[k..k+3][n], n = 8nb + lane/4,
//   k = 32ks + 4*(lane%4) + 16e.  bf16 m16n8k16: as before.
// w1/wf1 pair-permuted: img col n -> orig col (n>>1)+(n&1)*128
// =====================================================================
__global__ void k0_frags(const float* __restrict__ w1, const float* __restrict__ w2,
                         const float* __restrict__ wf1, const float* __restrict__ wf2)
{
    int i0 = blockIdx.x * blockDim.x + threadIdx.x, str = gridDim.x * blockDim.x;
    // w1 fp8 image: [ks4][half][nbp][lane][e4] = 8192 words
    for (int i = i0; i < 8192; i += str) {
        int e4 = i & 3, lane = (i >> 2) & 31, nbp = (i >> 7) & 7;
        int half = (i >> 10) & 1, ks = i >> 11;
        int nbg = half * 16 + 2 * nbp + (e4 >> 1);
        int e = e4 & 1;
        int n = 8 * nbg + (lane >> 2);
        int k = 32 * ks + 4 * (lane & 3) + 16 * e;
        int o = (n >> 1) + (n & 1) * 128;
        uint32_t w = 0;
        #pragma unroll
        for (int j = 0; j < 4; ++j) {
            __nv_fp8_e4m3 v(w1[(k + j) * 256 + o] * W1SCL);
            w |= (uint32_t)(*reinterpret_cast<uint8_t*>(&v)) << (8 * j);
        }
        g_fw1[i] = w;
    }
    // wf1 bf16 image: [ks8][half][nbp][lane][e4] = 16384 words
    for (int i = i0; i < 16384; i += str) {
        int e4 = i & 3, lane = (i >> 2) & 31, nbp = (i >> 7) & 7;
        int half = (i >> 10) & 1, ks = i >> 11;
        int nbg = half * 16 + 2 * nbp + (e4 >> 1);
        int e = e4 & 1;
        int n = 8 * nbg + (lane >> 2);
        int k = 16 * ks + 2 * (lane & 3) + 8 * e;
        int o = (n >> 1) + (n & 1) * 128;
        g_fwf1[i] = pack_bf2(wf1[k * 256 + o], wf1[(k + 1) * 256 + o]);
    }
    // n128 bf16 images: [ks8][nbp][lane][e4] = 8192 words
    for (int i = i0; i < 8192; i += str) {
        int e4 = i & 3, lane = (i >> 2) & 31, nbp = (i >> 7) & 7, ks = i >> 10;
        int nb = 2 * nbp + (e4 >> 1);
        int e = e4 & 1;
        int n = 8 * nb + (lane >> 2);
        int k = 16 * ks + 2 * (lane & 3) + 8 * e;
        g_fw2 [i] = pack_bf2(w2 [k * 128 + n], w2 [(k + 1) * 128 + n]);
        g_fwf2[i] = pack_bf2(wf2[k * 128 + n], wf2[(k + 1) * 128 + n]);
    }
}

// =====================================================================
// kA: 256 thr, 8 warps x 16 rows, 2 CTAs/SM.
//     LN1 (fp8 A-tile) -> fp8 mma(w1, 2 x n128) -> dw-affine + gate
//     -> g_s (bf16) + per-tile GAP.
// smem: a8[128*SA8] | bf16 gate tile[128*SA] | fw1 fp8 32KB | ew | ln | gap
// =====================================================================
#define KA_BT   18432                 // bf16 gate tile
#define KA_FW1  (KA_BT + 38912)       // 57344
#define KA_EW   (KA_FW1 + 32768)      // 90112
#define KA_LN   (KA_EW + 2048)        // 92160
#define KA_GAP  (KA_LN + 1024)        // 93184
#define KA_SMEM (KA_GAP + 4096)       // 97280

__global__ void __launch_bounds__(256, 2)
kA_spatial(const float* __restrict__ x,
           const float* __restrict__ ln1s, const float* __restrict__ ln1b,
           const float* __restrict__ b1,   const float* __restrict__ wdw,
           const float* __restrict__ bdw)
{
    extern __shared__ char sm[];
    const int tid = threadIdx.x, lane = tid & 31, warp = tid >> 5;
    const int q = lane & 3, r = lane >> 2, m0 = warp * 16;

    {
        uint4* dst = (uint4*)(sm + KA_FW1);
        const uint4* src = (const uint4*)g_fw1;
        for (int i = tid; i < 2048; i += 256) dst[i] = src[i];
        if (tid < 256) {
            int n = tid, o = (n >> 1) + (n & 1) * 128;
            float w = wdw[o];
            // acc = t @ (8*w1)  ->  fold 1/8 into the dw scale
            ((float2*)(sm + KA_EW))[n] = make_float2(w * (1.0f / W1SCL), b1[o] * w + bdw[o]);
        }
        if (tid < 128)
            ((float2*)(sm + KA_LN))[tid] = make_float2(ln1s[tid], ln1b[tid]);
    }
    __syncthreads();

    const float2* ewp = (const float2*)(sm + KA_EW);
    const float2* lnp = (const float2*)(sm + KA_LN);
    float* gapw = (float*)(sm + KA_GAP);
    const int pl = tid >> 1, h = tid & 1;

    for (int tile = blockIdx.x; tile < NT; tile += GRID_A) {
        // ---- LN1: thread = (pixel pl, channel half h) -> fp8 A-tile ----
        const float4* xr = (const float4*)x + ((size_t)(tile * 128 + pl)) * 32 + h * 16;
        float4 xv[16];
        float s1 = 0.f, s2 = 0.f;
        #pragma unroll
        for (int i = 0; i < 16; ++i) {
            xv[i] = xr[i];
            s1 += xv[i].x + xv[i].y + xv[i].z + xv[i].w;
            s2 += xv[i].x*xv[i].x + xv[i].y*xv[i].y + xv[i].z*xv[i].z + xv[i].w*xv[i].w;
        }
        s1 += __shfl_xor_sync(0xffffffffu, s1, 1);
        s2 += __shfl_xor_sync(0xffffffffu, s2, 1);
        const float mu = s1 * (1.f/128.f);
        const float rs = rsqrtf(fmaxf(s2 * (1.f/128.f) - mu*mu, 0.f) + EPS);

        char* row8 = sm + pl * SA8 + h * 64;
        #pragma unroll
        for (int j = 0; j < 8; ++j) {
            float4 v0 = xv[2*j], v1 = xv[2*j+1];
            int c = h * 64 + 8 * j;
            float2 p0 = lnp[c],   p1 = lnp[c+1], p2 = lnp[c+2], p3 = lnp[c+3];
            float2 p4 = lnp[c+4], p5 = lnp[c+5], p6 = lnp[c+6], p7 = lnp[c+7];
            uint32_t w0 = pack_e4m3x4((v0.x-mu)*rs*p0.x+p0.y, (v0.y-mu)*rs*p1.x+p1.y,
                                      (v0.z-mu)*rs*p2.x+p2.y, (v0.w-mu)*rs*p3.x+p3.y);
            uint32_t w1w = pack_e4m3x4((v1.x-mu)*rs*p4.x+p4.y, (v1.y-mu)*rs*p5.x+p5.y,
                                       (v1.z-mu)*rs*p6.x+p6.y, (v1.w-mu)*rs*p7.x+p7.y);
            *(uint2*)(row8 + j * 8) = make_uint2(w0, w1w);
        }
        __syncwarp();

        const char* a8r = sm + (m0 + r) * SA8;
        uint32_t gsave[16];

        #pragma unroll 1
        for (int half = 0; half < 2; ++half) {
            float acc[16][4];
            #pragma unroll
            for (int nb = 0; nb < 16; ++nb)
                { acc[nb][0]=0.f; acc[nb][1]=0.f; acc[nb][2]=0.f; acc[nb][3]=0.f; }

            #pragma unroll 2
            for (int ks = 0; ks < 4; ++ks) {
                int kb = 32 * ks + 4 * q;
                uint32_t a0 = *(const uint32_t*)(a8r + kb);
                uint32_t a1 = *(const uint32_t*)(a8r + 8 * SA8 + kb);
                uint32_t a2 = *(const uint32_t*)(a8r + kb + 16);
                uint32_t a3 = *(const uint32_t*)(a8r + 8 * SA8 + kb + 16);
                const uint4* fb = (const uint4*)(sm + KA_FW1) + (ks * 2 + half) * 256 + lane;
                #pragma unroll
                for (int nbp = 0; nbp < 8; ++nbp) {
                    uint4 b = fb[nbp * 32];
                    mma_fp8(acc[2*nbp],   a0, a1, a2, a3, b.x, b.y);
                    mma_fp8(acc[2*nbp+1], a0, a1, a2, a3, b.z, b.w);
                }
            }

            #pragma unroll
            for (int nb = 0; nb < 16; ++nb) {
                int nbg = half * 16 + nb;
                int n0 = 8 * nbg + 2 * q, j = 4 * nbg + q;
                float2 e0 = ewp[n0], e1 = ewp[n0 + 1];
                float lo = (acc[nb][0]*e0.x + e0.y) * (acc[nb][1]*e1.x + e1.y);
                float hi = (acc[nb][2]*e0.x + e0.y) * (acc[nb][3]*e1.x + e1.y);
                float g = lo + hi;
                g += __shfl_xor_sync(0xffffffffu, g, 4);
                g += __shfl_xor_sync(0xffffffffu, g, 8);
                g += __shfl_xor_sync(0xffffffffu, g, 16);
                if (r == 0) gapw[warp * 128 + j] = g;
                if (half == 0) {
                    gsave[nb] = pack_bf2(lo, hi);
                } else {
                    *(__nv_bfloat16*)(sm + KA_BT + (m0 + r)     * SA + j * 2) = __float2bfloat16(lo);
                    *(__nv_bfloat16*)(sm + KA_BT + (m0 + r + 8) * SA + j * 2) = __float2bfloat16(hi);
                }
            }
            __syncwarp();
        }
        #pragma unroll
        for (int nb = 0; nb < 16; ++nb) {
            int j = 4 * nb + q;
            float2 v = unpack_bf2(gsave[nb]);
            *(__nv_bfloat16*)(sm + KA_BT + (m0 + r)     * SA + j * 2) = __float2bfloat16(v.x);
            *(__nv_bfloat16*)(sm + KA_BT + (m0 + r + 8) * SA + j * 2) = __float2bfloat16(v.y);
        }
        __syncwarp();

        // ---- coalesced copy to g_s ----
        #pragma unroll
        for (int i = 0; i < 8; ++i) {
            int u = lane + 32 * i, row = u >> 4, ch = u & 15;
            uint4 v = *(const uint4*)(sm + KA_BT + (m0 + row) * SA + ch * 16);
            ((uint4*)g_s)[((size_t)(tile * 128 + m0 + row)) * 16 + ch] = v;
        }

        // ---- GAP partial: sum 8 warps in fixed order ----
        __syncthreads();
        if (tid < 128) {
            float s = 0.f;
            #pragma unroll
            for (int w = 0; w < 8; ++w) s += gapw[w * 128 + tid];
            g_gpart[tile * 128 + tid] = s;
        }
        __syncthreads();
    }
}

// =====================================================================
// k2_se: merged GAP reduce (4-way over tiles) + SE matvec (4-way over k)
// =====================================================================
__global__ void k2_se(const float* __restrict__ wse, const float* __restrict__ bse)
{
    __shared__ float red[4][128];
    __shared__ float gap[128];
    __shared__ float ps[4][128];
    const int b = blockIdx.x, tid = threadIdx.x;
    const int c = tid & 127, g = tid >> 7;

    float s = 0.f;
    const float* src = g_gpart + (size_t)(b * TPB + g * 72) * 128 + c;
    #pragma unroll 8
    for (int i = 0; i < 72; ++i) s += src[(size_t)i * 128];
    red[g][c] = s;
    __syncthreads();
    if (tid < 128)
        gap[tid] = ((red[0][tid] + red[1][tid]) + (red[2][tid] + red[3][tid])) * (1.f / PIXPB);
    __syncthreads();

    float a = 0.f;
    #pragma unroll 8
    for (int kk = 0; kk < 32; ++kk) {
        int k = 32 * g + kk;
        a += gap[k] * wse[k * 128 + c];
    }
    ps[g][c] = a;
    __syncthreads();
    if (tid < 128)
        g_att[b * 128 + tid] = bse[tid] +
            ((ps[0][tid] + ps[1][tid]) + (ps[2][tid] + ps[3][tid]));
}

// =====================================================================
// kB: 256 thr, 8 warps x 16 rows, batch-fixed CTAs (18 per batch).
//     att folded into w2 frags. cp.async cross-tile prefetch. ks unroll 2.
//     (unchanged from R11 winner)
// =====================================================================
#define KB_XM    38912
#define KB_FWF1  (KB_XM + 67584)
#define KB_FW2   (KB_FWF1 + 65536)
#define KB_E2    (KB_FW2 + 32768)
#define KB_ELN   (KB_E2 + 1024)
#define KB_EBF1  (KB_ELN + 1024)
#define KB_EGAM  (KB_EBF1 + 1024)
#define KB_ATT   (KB_EGAM + 1024)
#define KB_SMEM  (KB_ATT + 512)

__global__ void __launch_bounds__(256, 1)
kB_ffn(const float* __restrict__ x,
       const float* __restrict__ b2,   const float* __restrict__ beta,
       const float* __restrict__ ln2s, const float* __restrict__ ln2b,
       const float* __restrict__ bf1,  const float* __restrict__ bf2,
       const float* __restrict__ gamma, float* __restrict__ out)
{
    extern __shared__ char sm[];
    const int tid = threadIdx.x, lane = tid & 31, warp = tid >> 5;
    const int q = lane & 3, r = lane >> 2, m0 = warp * 16;
    const uint32_t sm_base = smem_u32(sm);
    const int batch = blockIdx.x / 18, sub = blockIdx.x % 18;
    const int tbase = batch * TPB + sub;

    {
        uint4* d1 = (uint4*)(sm + KB_FWF1);
        const uint4* s1p = (const uint4*)g_fwf1;
        for (int i = tid; i < 4096; i += 256) d1[i] = s1p[i];
        uint4* d2 = (uint4*)(sm + KB_FW2);
        const uint4* s2p = (const uint4*)g_fw2;
        for (int i = tid; i < 2048; i += 256) d2[i] = s2p[i];
        if (tid < 128) {
            float be = beta[tid], ga = gamma[tid];
            ((float2*)(sm + KB_E2  ))[tid] = make_float2(be, be * b2[tid]);
            ((float2*)(sm + KB_ELN ))[tid] = make_float2(ln2s[tid], ln2b[tid]);
            ((float2*)(sm + KB_EGAM))[tid] = make_float2(ga, ga * bf2[tid]);
            ((float*)(sm + KB_ATT))[tid] = g_att[batch * 128 + tid];
        }
        if (tid < 256) {
            int n = tid, o = (n >> 1) + (n & 1) * 128;
            ((float*)(sm + KB_EBF1))[n] = bf1[o];
        }
    }
    __syncthreads();

    // ---- scale staged w2 frags by att (once per CTA; pair-packed layout) ----
    {
        const float* attv = (const float*)(sm + KB_ATT);
        uint4* p = (uint4*)(sm + KB_FW2);
        for (int i = tid; i < 2048; i += 256) {
            int lane2 = i & 31, ks = i >> 8;
            int k0 = 16 * ks + 2 * (lane2 & 3);
            uint4 v = p[i];
            float2 w0 = unpack_bf2(v.x), w1v = unpack_bf2(v.y);
            float2 w2v = unpack_bf2(v.z), w3v = unpack_bf2(v.w);
            v.x = pack_bf2(w0.x  * attv[k0],     w0.y  * attv[k0 + 1]);
            v.y = pack_bf2(w1v.x * attv[k0 + 8], w1v.y * attv[k0 + 9]);
            v.z = pack_bf2(w2v.x * attv[k0],     w2v.y * attv[k0 + 1]);
            v.w = pack_bf2(w3v.x * attv[k0 + 8], w3v.y * attv[k0 + 9]);
            p[i] = v;
        }
    }
    __syncthreads();

    const float2* e2p  = (const float2*)(sm + KB_E2);
    const float2* elnp = (const float2*)(sm + KB_ELN);
    const float*  ebfp = (const float*)(sm + KB_EBF1);
    const float2* egap = (const float2*)(sm + KB_EGAM);
    float* xms = (float*)(sm + KB_XM);
    const int pl = tid >> 1, h = tid & 1;

    auto prefetch_s = [&](int t) {
        const char* sg = (const char*)(g_s + ((size_t)(t * 128 + pl)) * 64) + h * 128;
        uint32_t dst = sm_base + (uint32_t)pl * SA + h * 128;
        #pragma unroll
        for (int j = 0; j < 8; ++j)
            CP_ASYNC16(dst + j * 16, sg + j * 16);
    };
    auto prefetch_x = [&](int t) {
        const float* xg = x + ((size_t)(t * 128 + m0)) * 128;
        #pragma unroll
        for (int i = 0; i < 16; ++i) {
            int gidx = i * 32 + lane;
            int row = gidx >> 5, c16 = gidx & 31;
            uint32_t dst = sm_base + KB_XM + (uint32_t)(m0 + row) * 528 + c16 * 16;
            CP_ASYNC16(dst, xg + (size_t)row * 128 + c16 * 4);
        }
    };

    prefetch_s(tbase); CP_COMMIT();
    prefetch_x(tbase); CP_COMMIT();

    #pragma unroll 1
    for (int it = 0; it < 16; ++it) {
        const int tile = tbase + 18 * it;
        const char* ar0 = sm + (m0 + r) * SA;

        CP_WAIT1();
        __syncwarp();

        // ---- GEMM w2 (frags pre-scaled by att; A = s) ----
        float acc[16][4];
        #pragma unroll
        for (int nb = 0; nb < 16; ++nb)
            { acc[nb][0]=0.f; acc[nb][1]=0.f; acc[nb][2]=0.f; acc[nb][3]=0.f; }
        #pragma unroll 2
        for (int ks = 0; ks < 8; ++ks) {
            int kb = 32 * ks + 4 * q;
            uint32_t a0 = *(const uint32_t*)(ar0 + kb);
            uint32_t a1 = *(const uint32_t*)(ar0 + 8 * SA + kb);
            uint32_t a2 = *(const uint32_t*)(ar0 + kb + 16);
            uint32_t a3 = *(const uint32_t*)(ar0 + 8 * SA + kb + 16);
            const uint4* fb = (const uint4*)(sm + KB_FW2) + ks * 256 + lane;
            #pragma unroll
            for (int nbp = 0; nbp < 8; ++nbp) {
                uint4 b = fb[nbp * 32];
                mma_bf16(acc[2*nbp],   a0, a1, a2, a3, b.x, b.y);
                mma_bf16(acc[2*nbp+1], a0, a1, a2, a3, b.z, b.w);
            }
        }

        // ---- xm = x + beta*(d+b2); stash f32; LN2 stats via quad shfl ----
        CP_WAIT0();
        __syncwarp();
        float s1a = 0.f, s2a = 0.f, s1b = 0.f, s2b = 0.f;
        #pragma unroll
        for (int nb = 0; nb < 16; ++nb) {
            int n0 = 8 * nb + 2 * q;
            float2 e0 = e2p[n0], e1 = e2p[n0 + 1];
            float* pa = xms + (m0 + r)     * 132 + n0;
            float* pb = xms + (m0 + r + 8) * 132 + n0;
            float2 xa = *(float2*)pa;
            float2 xb = *(float2*)pb;
            float m00 = xa.x + acc[nb][0]*e0.x + e0.y;
            float m01 = xa.y + acc[nb][1]*e1.x + e1.y;
            float m10 = xb.x + acc[nb][2]*e0.x + e0.y;
            float m11 = xb.y + acc[nb][3]*e1.x + e1.y;
            *(float2*)pa = make_float2(m00, m01);
            *(float2*)pb = make_float2(m10, m11);
            s1a += m00 + m01; s2a += m00*m00 + m01*m01;
            s1b += m10 + m11; s2b += m10*m10 + m11*m11;
        }
        s1a += __shfl_xor_sync(0xffffffffu, s1a, 1); s1a += __shfl_xor_sync(0xffffffffu, s1a, 2);
        s2a += __shfl_xor_sync(0xffffffffu, s2a, 1); s2a += __shfl_xor_sync(0xffffffffu, s2a, 2);
        s1b += __shfl_xor_sync(0xffffffffu, s1b, 1); s1b += __shfl_xor_sync(0xffffffffu, s1b, 2);
        s2b += __shfl_xor_sync(0xffffffffu, s2b, 1); s2b += __shfl_xor_sync(0xffffffffu, s2b, 2);
        const float mua = s1a * (1.f/128.f);
        const float rsa = rsqrtf(fmaxf(s2a * (1.f/128.f) - mua*mua, 0.f) + EPS);
        const float mub = s1b * (1.f/128.f);
        const float rsb = rsqrtf(fmaxf(s2b * (1.f/128.f) - mub*mub, 0.f) + EPS);

        // ---- A2 = LN2(xm) -> atile bf16 ----
        #pragma unroll
        for (int nb = 0; nb < 16; ++nb) {
            int n0 = 8 * nb + 2 * q;
            float2 p0 = elnp[n0], p1 = elnp[n0 + 1];
            float2 va = *(const float2*)(xms + (m0 + r)     * 132 + n0);
            float2 vb = *(const float2*)(xms + (m0 + r + 8) * 132 + n0);
            *(uint32_t*)(sm + (m0 + r)     * SA + n0 * 2) =
                pack_bf2((va.x-mua)*rsa*p0.x+p0.y, (va.y-mua)*rsa*p1.x+p1.y);
            *(uint32_t*)(sm + (m0 + r + 8) * SA + n0 * 2) =
                pack_bf2((vb.x-mub)*rsb*p0.x+p0.y, (vb.y-mub)*rsb*p1.x+p1.y);
        }
        __syncwarp();

        // ---- GEMM wf1 (paired, 2 x n128 passes) ----
        uint32_t gsave[16];
        #pragma unroll 1
        for (int half = 0; half < 2; ++half) {
            float acc2[16][4];
            #pragma unroll
            for (int nb = 0; nb < 16; ++nb)
                { acc2[nb][0]=0.f; acc2[nb][1]=0.f; acc2[nb][2]=0.f; acc2[nb][3]=0.f; }
            #pragma unroll 2
            for (int ks = 0; ks < 8; ++ks) {
                int kb = 32 * ks + 4 * q;
                uint32_t a0 = *(const uint32_t*)(ar0 + kb);
                uint32_t a1 = *(const uint32_t*)(ar0 + 8 * SA + kb);
                uint32_t a2 = *(const uint32_t*)(ar0 + kb + 16);
                uint32_t a3 = *(const uint32_t*)(ar0 + 8 * SA + kb + 16);
                const uint4* fb = (const uint4*)(sm + KB_FWF1) + (ks * 2 + half) * 256 + lane;
                #pragma unroll
                for (int nbp = 0; nbp < 8; ++nbp) {
                    uint4 b = fb[nbp * 32];
                    mma_bf16(acc2[2*nbp],   a0, a1, a2, a3, b.x, b.y);
                    mma_bf16(acc2[2*nbp+1], a0, a1, a2, a3, b.z, b.w);
                }
            }
            #pragma unroll
            for (int nb = 0; nb < 16; ++nb) {
                int nbg = half * 16 + nb;
                int n0 = 8 * nbg + 2 * q, j = 4 * nbg + q;
                float e0 = ebfp[n0], e1 = ebfp[n0 + 1];
                float lo = (acc2[nb][0] + e0) * (acc2[nb][1] + e1);
                float hi = (acc2[nb][2] + e0) * (acc2[nb][3] + e1);
                if (half == 0) {
                    gsave[nb] = pack_bf2(lo, hi);
                } else {
                    *(__nv_bfloat16*)(sm + (m0 + r)     * SA + j * 2) = __float2bfloat16(lo);
                    *(__nv_bfloat16*)(sm + (m0 + r + 8) * SA + j * 2) = __float2bfloat16(hi);
                }
            }
            __syncwarp();
        }
        #pragma unroll
        for (int nb = 0; nb < 16; ++nb) {
            int j = 4 * nb + q;
            float2 v = unpack_bf2(gsave[nb]);
            *(__nv_bfloat16*)(sm + (m0 + r)     * SA + j * 2) = __float2bfloat16(v.x);
            *(__nv_bfloat16*)(sm + (m0 + r + 8) * SA + j * 2) = __float2bfloat16(v.y);
        }
        __syncwarp();

        // ---- GEMM wf2 (n128), frags via LDG.128 ----
        float acc3[16][4];
        #pragma unroll
        for (int nb = 0; nb < 16; ++nb)
            { acc3[nb][0]=0.f; acc3[nb][1]=0.f; acc3[nb][2]=0.f; acc3[nb][3]=0.f; }
        #pragma unroll 2
        for (int ks = 0; ks < 8; ++ks) {
            int kb = 32 * ks + 4 * q;
            uint32_t a0 = *(const uint32_t*)(ar0 + kb);
            uint32_t a1 = *(const uint32_t*)(ar0 + 8 * SA + kb);
            uint32_t a2 = *(const uint32_t*)(ar0 + kb + 16);
            uint32_t a3 = *(const uint32_t*)(ar0 + 8 * SA + kb + 16);
            const uint4* fb = (const uint4*)g_fwf2 + ks * 256 + lane;
            #pragma unroll
            for (int nbp = 0; nbp < 8; ++nbp) {
                uint4 b = __ldg(fb + nbp * 32);
                mma_bf16(acc3[2*nbp],   a0, a1, a2, a3, b.x, b.y);
                mma_bf16(acc3[2*nbp+1], a0, a1, a2, a3, b.z, b.w);
            }
        }

        // ---- prefetch next tile's s (atile is dead now) ----
        if (it < 15) { prefetch_s(tile + 18); CP_COMMIT(); }

        // ---- out = xm + gamma*(d+bf2) ----
        float* or0 = out + ((size_t)(tile * 128 + m0 + r)) * 128;
        float* or8 = or0 + (size_t)8 * 128;
        #pragma unroll
        for (int nb = 0; nb < 16; ++nb) {
            int n0 = 8 * nb + 2 * q;
            float2 g0 = egap[n0], g1 = egap[n0 + 1];
            float2 va = *(const float2*)(xms + (m0 + r)     * 132 + n0);
            float2 vb = *(const float2*)(xms + (m0 + r + 8) * 132 + n0);
            *(float2*)(or0 + n0) = make_float2(va.x + acc3[nb][0]*g0.x + g0.y,
                                               va.y + acc3[nb][1]*g1.x + g1.y);
            *(float2*)(or8 + n0) = make_float2(vb.x + acc3[nb][2]*g0.x + g0.y,
                                               vb.y + acc3[nb][3]*g1.x + g1.y);
        }

        // ---- prefetch next tile's x (xm region is dead now) ----
        if (it < 15) { prefetch_x(tile + 18); CP_COMMIT(); }
        __syncwarp();
    }
}

// =====================================================================
// launch
// =====================================================================
extern "C" void kernel_launch(void* const* d_in, const int* in_sizes, int n_in,
                              void* d_out, int out_size)
{
    (void)in_sizes; (void)n_in; (void)out_size;
    const float* x     = (const float*)d_in[0];
    const float* ln1s  = (const float*)d_in[1];
    const float* ln1b  = (const float*)d_in[2];
    const float* w1    = (const float*)d_in[3];
    const float* b1    = (const float*)d_in[4];
    const float* wdw   = (const float*)d_in[5];
    const float* bdw   = (const float*)d_in[6];
    const float* wse   = (const float*)d_in[7];
    const float* bse   = (const float*)d_in[8];
    const float* w2    = (const float*)d_in[9];
    const float* b2    = (const float*)d_in[10];
    const float* ln2s  = (const float*)d_in[11];
    const float* ln2b  = (const float*)d_in[12];
    const float* wf1   = (const float*)d_in[13];
    const float* bf1   = (const float*)d_in[14];
    const float* wf2   = (const float*)d_in[15];
    const float* bf2   = (const float*)d_in[16];
    const float* beta  = (const float*)d_in[17];
    const float* gamma = (const float*)d_in[18];
    float* out = (float*)d_out;

    cudaFuncSetAttribute(kA_spatial, cudaFuncAttributeMaxDynamicSharedMemorySize, KA_SMEM);
    cudaFuncSetAttribute(kB_ffn,     cudaFuncAttributeMaxDynamicSharedMemorySize, KB_SMEM);

    k0_frags<<<64, 256>>>(w1, w2, wf1, wf2);
    kA_spatial<<<GRID_A, 256, KA_SMEM>>>(x, ln1s, ln1b, b1, wdw, bdw);
    k2_se<<<B_, 512>>>(wse, bse);
    kB_ffn<<<GRID_B, 256, KB_SMEM>>>(x, b2, beta, ln2s, ln2b, bf1, bf2, gamma, out);
}